// round 1
// baseline (speedup 1.0000x reference)
#include <cuda_runtime.h>
#include <cuda_bf16.h>
#include <math.h>
#include <stdint.h>

// Problem constants (fixed by setup_inputs)
#define B 4
#define C 192
#define C3 576          // 3*C
#define NH 4
#define CPH 48          // C / NH
#define HW 65536        // 256*256
#define IMG 256

// ---------------- device scratch (no allocs allowed) ----------------
__device__ float g_qkv[(size_t)B * C3 * HW];       // after 1x1 conv
__device__ float g_qkv_dw[(size_t)B * C3 * HW];    // after depthwise conv
__device__ float g_sumsq[2][B * C];                // [0]=q, [1]=k   sum of squares per row
__device__ float g_gram_part[(size_t)B * NH * 64 * CPH * CPH]; // split-K partials (64 chunks)
__device__ float g_gram[B * NH * CPH * CPH];
__device__ float g_attn[B * NH * CPH * CPH];
__device__ float g_M[B * C * C];                   // fused proj @ blockdiag(attn)

// ---------------- SGEMM: C[b][m][n] = sum_k A[b][m][k] * X[b][k][n], K=192, N=65536 -----
// BM=64, BN=128, BK=16, 128 threads, 8x8 per thread.
#define BM 64
#define BN 128
#define BKt 16

__global__ __launch_bounds__(128) void sgemm_k192(
    const float* __restrict__ A, size_t aStride,
    const float* __restrict__ X, size_t xStride,
    float* __restrict__ Cc, size_t cStride)
{
    const int b = blockIdx.z;
    A  += (size_t)b * aStride;
    X  += (size_t)b * xStride;
    Cc += (size_t)b * cStride;

    const int n0 = blockIdx.x * BN;
    const int m0 = blockIdx.y * BM;

    __shared__ float As[BKt][BM];
    __shared__ float Bs[BKt][BN];

    const int t  = threadIdx.x;
    const int tx = t & 15;   // 0..15 -> 8 cols each
    const int ty = t >> 4;   // 0..7  -> 8 rows each

    float acc[8][8];
    #pragma unroll
    for (int i = 0; i < 8; i++)
        #pragma unroll
        for (int j = 0; j < 8; j++) acc[i][j] = 0.f;

    for (int k0 = 0; k0 < 192; k0 += BKt) {
        // Load A tile: 64 rows x 16 k = 256 float4 (4 k's per float4), transpose into As[k][m]
        #pragma unroll
        for (int i = 0; i < 2; i++) {
            int e   = t + i * 128;          // 0..255
            int row = e >> 2;               // m 0..63
            int c4  = (e & 3) * 4;          // k offset 0,4,8,12
            float4 w4 = *(const float4*)&A[(size_t)(m0 + row) * 192 + k0 + c4];
            As[c4 + 0][row] = w4.x;
            As[c4 + 1][row] = w4.y;
            As[c4 + 2][row] = w4.z;
            As[c4 + 3][row] = w4.w;
        }
        // Load B tile: 16 k x 128 n = 512 float4
        #pragma unroll
        for (int i = 0; i < 4; i++) {
            int e   = t + i * 128;          // 0..511
            int row = e >> 5;               // k 0..15
            int col = (e & 31) * 4;         // n offset
            *(float4*)&Bs[row][col] =
                *(const float4*)&X[(size_t)(k0 + row) * HW + n0 + col];
        }
        __syncthreads();

        #pragma unroll
        for (int k = 0; k < BKt; k++) {
            float a[8], bb[8];
            *(float4*)&a[0]  = *(const float4*)&As[k][ty * 8];
            *(float4*)&a[4]  = *(const float4*)&As[k][ty * 8 + 4];
            *(float4*)&bb[0] = *(const float4*)&Bs[k][tx * 8];
            *(float4*)&bb[4] = *(const float4*)&Bs[k][tx * 8 + 4];
            #pragma unroll
            for (int i = 0; i < 8; i++)
                #pragma unroll
                for (int j = 0; j < 8; j++)
                    acc[i][j] += a[i] * bb[j];
        }
        __syncthreads();
    }

    #pragma unroll
    for (int i = 0; i < 8; i++) {
        float* crow = &Cc[(size_t)(m0 + ty * 8 + i) * HW + n0 + tx * 8];
        *(float4*)&crow[0] = *(const float4*)&acc[i][0];
        *(float4*)&crow[4] = *(const float4*)&acc[i][4];
    }
}

// ---------------- depthwise 3x3 conv, SAME padding, cross-correlation ----------------
__global__ void k_dwconv(const float* __restrict__ w)
{
    const int ch = blockIdx.y;
    const int b  = blockIdx.z;
    __shared__ float wk[9];
    if (threadIdx.x < 9) wk[threadIdx.x] = w[ch * 9 + threadIdx.x];
    __syncthreads();

    const int p = blockIdx.x * blockDim.x + threadIdx.x;  // 0..65535
    const int y = p >> 8;
    const int x = p & 255;
    const float* src = g_qkv + ((size_t)b * C3 + ch) * HW;

    float s = 0.f;
    #pragma unroll
    for (int dy = -1; dy <= 1; dy++) {
        int yy = y + dy;
        if (yy < 0 || yy >= IMG) continue;
        #pragma unroll
        for (int dx = -1; dx <= 1; dx++) {
            int xx = x + dx;
            if (xx < 0 || xx >= IMG) continue;
            s += wk[(dy + 1) * 3 + (dx + 1)] * src[yy * IMG + xx];
        }
    }
    g_qkv_dw[((size_t)b * C3 + ch) * HW + p] = s;
}

// ---------------- per-row sum of squares for q (z=0) and k (z=1) ----------------
__global__ void k_sumsq()
{
    const int ch = blockIdx.x;   // 0..191
    const int b  = blockIdx.y;   // 0..3
    const int z  = blockIdx.z;   // 0=q, 1=k
    const int t  = threadIdx.x;

    const float4* row = (const float4*)(g_qkv_dw + ((size_t)b * C3 + z * C + ch) * HW);
    float s = 0.f;
    for (int i = t; i < HW / 4; i += 256) {
        float4 v = row[i];
        s += v.x * v.x + v.y * v.y + v.z * v.z + v.w * v.w;
    }
    __shared__ float red[256];
    red[t] = s;
    __syncthreads();
    for (int st = 128; st > 0; st >>= 1) {
        if (t < st) red[t] += red[t + st];
        __syncthreads();
    }
    if (t == 0) g_sumsq[z][b * C + ch] = red[0];
}

// ---------------- Gram matrix partials: gram[b,h,c,d] = sum_n q[c,n]k[d,n] ----------------
// 64 n-chunks of 1024; block = 64 threads (8x8), 6x6 outputs each. Deterministic (no atomics).
__global__ __launch_bounds__(64) void k_gram()
{
    const int chunk = blockIdx.x;  // 0..63
    const int h     = blockIdx.y;
    const int b     = blockIdx.z;

    __shared__ float Qs[32][49];
    __shared__ float Ks[32][49];

    const float* qb = g_qkv_dw + ((size_t)b * C3 + h * CPH) * HW + chunk * 1024;
    const float* kb = qb + (size_t)C * HW;

    const int t  = threadIdx.x;
    const int tx = t & 7;
    const int ty = t >> 3;

    float acc[6][6];
    #pragma unroll
    for (int i = 0; i < 6; i++)
        #pragma unroll
        for (int j = 0; j < 6; j++) acc[i][j] = 0.f;

    for (int nt = 0; nt < 1024; nt += 32) {
        #pragma unroll
        for (int i = 0; i < 24; i++) {
            int e  = t + i * 64;
            int c  = e >> 5;       // row 0..47
            int kk = e & 31;       // n within tile
            Qs[kk][c] = qb[(size_t)c * HW + nt + kk];
            Ks[kk][c] = kb[(size_t)c * HW + nt + kk];
        }
        __syncthreads();
        #pragma unroll 8
        for (int kk = 0; kk < 32; kk++) {
            float a[6], bb[6];
            #pragma unroll
            for (int i = 0; i < 6; i++) a[i]  = Qs[kk][ty * 6 + i];
            #pragma unroll
            for (int j = 0; j < 6; j++) bb[j] = Ks[kk][tx * 6 + j];
            #pragma unroll
            for (int i = 0; i < 6; i++)
                #pragma unroll
                for (int j = 0; j < 6; j++)
                    acc[i][j] += a[i] * bb[j];
        }
        __syncthreads();
    }

    const size_t base = (((size_t)(b * NH + h)) * 64 + chunk) * (CPH * CPH);
    #pragma unroll
    for (int i = 0; i < 6; i++)
        #pragma unroll
        for (int j = 0; j < 6; j++)
            g_gram_part[base + (ty * 6 + i) * CPH + tx * 6 + j] = acc[i][j];
}

// ---------------- reduce Gram partials (fixed order => deterministic) ----------------
__global__ void k_gram_reduce()
{
    const int idx = blockIdx.x * blockDim.x + threadIdx.x;  // 0..36863
    if (idx >= B * NH * CPH * CPH) return;
    const int bh = idx / (CPH * CPH);
    const int cd = idx % (CPH * CPH);
    float s = 0.f;
    for (int ck = 0; ck < 64; ck++)
        s += g_gram_part[((size_t)bh * 64 + ck) * (CPH * CPH) + cd];
    g_gram[idx] = s;
}

// ---------------- normalize + temperature + softmax over d ----------------
__global__ void k_softmax(const float* __restrict__ temperature)
{
    const int bh = blockIdx.x;          // 0..15
    const int b  = bh >> 2;
    const int h  = bh & 3;
    const int c  = threadIdx.x;
    if (c >= CPH) return;

    const float tv = temperature[h];
    const float nq = fmaxf(sqrtf(g_sumsq[0][b * C + h * CPH + c]), 1e-12f);

    float vals[CPH];
    float mx = -1e30f;
    #pragma unroll 4
    for (int d = 0; d < CPH; d++) {
        float nk = fmaxf(sqrtf(g_sumsq[1][b * C + h * CPH + d]), 1e-12f);
        float v  = g_gram[bh * (CPH * CPH) + c * CPH + d] / (nq * nk) * tv;
        vals[d] = v;
        mx = fmaxf(mx, v);
    }
    float sum = 0.f;
    #pragma unroll 4
    for (int d = 0; d < CPH; d++) {
        vals[d] = expf(vals[d] - mx);
        sum += vals[d];
    }
    const float inv = 1.f / sum;
    #pragma unroll 4
    for (int d = 0; d < CPH; d++)
        g_attn[bh * (CPH * CPH) + c * CPH + d] = vals[d] * inv;
}

// ---------------- M[b][o][h*48+d] = sum_cl proj_w[o][h*48+cl] * attn[b,h][cl][d] ----------------
__global__ void k_mixW(const float* __restrict__ proj_w)
{
    const int o  = blockIdx.x;       // 0..191
    const int b  = blockIdx.y;       // 0..3
    const int dg = threadIdx.x;      // 0..191
    const int h  = dg / CPH;
    const int d  = dg % CPH;
    float s = 0.f;
    #pragma unroll 8
    for (int cl = 0; cl < CPH; cl++)
        s += proj_w[o * C + h * CPH + cl] *
             g_attn[((size_t)(b * NH + h)) * (CPH * CPH) + cl * CPH + d];
    g_M[((size_t)b * C + o) * C + dg] = s;
}

// ---------------- launch ----------------
extern "C" void kernel_launch(void* const* d_in, const int* in_sizes, int n_in,
                              void* d_out, int out_size)
{
    const float* x      = (const float*)d_in[0];
    const float* qkv_w  = (const float*)d_in[1];
    const float* dw_w   = (const float*)d_in[2];
    const float* proj_w = (const float*)d_in[3];
    const float* temp   = (const float*)d_in[4];
    float* out = (float*)d_out;

    float *p_qkv, *p_qkv_dw, *p_M;
    cudaGetSymbolAddress((void**)&p_qkv, g_qkv);
    cudaGetSymbolAddress((void**)&p_qkv_dw, g_qkv_dw);
    cudaGetSymbolAddress((void**)&p_M, g_M);

    // 1) qkv = x @ qkv_w^T  (per batch GEMM [576x192]@[192x65536])
    sgemm_k192<<<dim3(HW / BN, C3 / BM, B), 128>>>(
        qkv_w, 0, x, (size_t)C * HW, p_qkv, (size_t)C3 * HW);

    // 2) 3x3 depthwise conv
    k_dwconv<<<dim3(HW / 256, C3, B), 256>>>(dw_w);

    // 3) row sum-of-squares for q and k
    k_sumsq<<<dim3(C, B, 2), 256>>>();

    // 4) Gram partials + reduce
    k_gram<<<dim3(64, NH, B), 64>>>();
    k_gram_reduce<<<(B * NH * CPH * CPH + 255) / 256, 256>>>();

    // 5) normalize + softmax, then fuse proj with attn into M
    k_softmax<<<B * NH, 64>>>(temp);
    k_mixW<<<dim3(C, B), C>>>(proj_w);

    // 6) out = M @ v  (per batch GEMM [192x192]@[192x65536])
    sgemm_k192<<<dim3(HW / BN, C / BM, B), 128>>>(
        p_M, (size_t)C * C, p_qkv_dw + (size_t)2 * C * HW, (size_t)C3 * HW,
        out, (size_t)C * HW);
}

// round 2
// speedup vs baseline: 2.0016x; 2.0016x over previous
#include <cuda_runtime.h>
#include <cuda_bf16.h>
#include <math.h>
#include <stdint.h>

// Problem constants (fixed by setup_inputs)
#define B 4
#define C 192
#define C3 576          // 3*C
#define NH 4
#define CPH 48          // C / NH
#define HW 65536        // 256*256
#define IMG 256

// ---------------- device scratch (no allocs allowed) ----------------
__device__ float g_qkv[(size_t)B * C3 * HW];          // after 1x1 conv (fp32)
__device__ __nv_bfloat16 g_dw_hi[(size_t)B * C3 * HW]; // after depthwise conv, hi part
__device__ __nv_bfloat16 g_dw_lo[(size_t)B * C3 * HW]; // lo part
__device__ __nv_bfloat16 g_x_hi[(size_t)B * C * HW];
__device__ __nv_bfloat16 g_x_lo[(size_t)B * C * HW];
__device__ __nv_bfloat16 g_w_hi[C3 * C];
__device__ __nv_bfloat16 g_w_lo[C3 * C];
__device__ __nv_bfloat16 g_M_hi[B * C * C];
__device__ __nv_bfloat16 g_M_lo[B * C * C];
__device__ float g_ssq_part[B * 2 * C * 256];          // per-row partial sumsq (q,k)
__device__ float g_sumsq[2][B * C];
__device__ float g_gram_part[(size_t)B * NH * 64 * CPH * CPH];
__device__ float g_gram[B * NH * CPH * CPH];
__device__ float g_attn[B * NH * CPH * CPH];
__device__ float g_M[B * C * C];

// ---------------- fp32 -> bf16 hi/lo split ----------------
__global__ void k_cvt(const float* __restrict__ src,
                      __nv_bfloat16* __restrict__ hi,
                      __nv_bfloat16* __restrict__ lo, int n4)
{
    int i = blockIdx.x * 256 + threadIdx.x;
    if (i >= n4) return;
    float4 v = ((const float4*)src)[i];
    __nv_bfloat16 h[4], l[4];
    float vv[4] = {v.x, v.y, v.z, v.w};
    #pragma unroll
    for (int j = 0; j < 4; j++) {
        h[j] = __float2bfloat16_rn(vv[j]);
        l[j] = __float2bfloat16_rn(vv[j] - __bfloat162float(h[j]));
    }
    ((uint2*)hi)[i] = *(uint2*)h;
    ((uint2*)lo)[i] = *(uint2*)l;
}

// ---------------- bf16-split GEMM via mma.sync (HMMA) ----------------
// C[b][m][n] = sum_k (Ahi+Alo)[m][k] * (Xhi+Xlo)[k][n], K=192, N=65536
// BM=64, BN=128, BK=32, 256 threads (8 warps in 2x4), warp tile 32x32.
#define GBM 64
#define GBN 128
#define GBK 32

__device__ __forceinline__ void ldsm_x4(uint32_t& r0, uint32_t& r1, uint32_t& r2, uint32_t& r3, uint32_t addr) {
    asm volatile("ldmatrix.sync.aligned.m8n8.x4.shared.b16 {%0,%1,%2,%3}, [%4];"
                 : "=r"(r0), "=r"(r1), "=r"(r2), "=r"(r3) : "r"(addr));
}
__device__ __forceinline__ void ldsm_x2t(uint32_t& r0, uint32_t& r1, uint32_t addr) {
    asm volatile("ldmatrix.sync.aligned.m8n8.x2.trans.shared.b16 {%0,%1}, [%2];"
                 : "=r"(r0), "=r"(r1) : "r"(addr));
}
__device__ __forceinline__ void mma16816(float* d, const uint32_t* a, const uint32_t* b) {
    asm volatile("mma.sync.aligned.m16n8k16.row.col.f32.bf16.bf16.f32 "
                 "{%0,%1,%2,%3}, {%4,%5,%6,%7}, {%8,%9}, {%0,%1,%2,%3};"
                 : "+f"(d[0]), "+f"(d[1]), "+f"(d[2]), "+f"(d[3])
                 : "r"(a[0]), "r"(a[1]), "r"(a[2]), "r"(a[3]), "r"(b[0]), "r"(b[1]));
}

__global__ __launch_bounds__(256) void gemm_bf16(
    const __nv_bfloat16* __restrict__ Ahi, const __nv_bfloat16* __restrict__ Alo, size_t aBatch,
    const __nv_bfloat16* __restrict__ Xhi, const __nv_bfloat16* __restrict__ Xlo, size_t xBatch,
    float* __restrict__ Cc, size_t cBatch)
{
    const int b = blockIdx.z;
    Ahi += (size_t)b * aBatch;  Alo += (size_t)b * aBatch;
    Xhi += (size_t)b * xBatch;  Xlo += (size_t)b * xBatch;
    Cc  += (size_t)b * cBatch;

    const int n0 = blockIdx.x * GBN;
    const int m0 = blockIdx.y * GBM;

    __shared__ __nv_bfloat16 As[2][GBM][40];    // [hi/lo][m][k], pad 32->40
    __shared__ __nv_bfloat16 Bs[2][GBK][136];   // [hi/lo][k][n], pad 128->136

    const int t    = threadIdx.x;
    const int lane = t & 31;
    const int w    = t >> 5;
    const int wm   = w & 1;     // 0..1 -> m offset
    const int wn   = w >> 1;    // 0..3 -> n offset

    float acc[2][4][4];
    #pragma unroll
    for (int mi = 0; mi < 2; mi++)
        #pragma unroll
        for (int ni = 0; ni < 4; ni++)
            #pragma unroll
            for (int r = 0; r < 4; r++) acc[mi][ni][r] = 0.f;

    for (int k0 = 0; k0 < 192; k0 += GBK) {
        // A tiles: 64 rows x 32 k, 8 bf16 per thread per array
        {
            int r  = t >> 2;
            int kc = (t & 3) * 8;
            *(uint4*)&As[0][r][kc] = *(const uint4*)&Ahi[(size_t)(m0 + r) * 192 + k0 + kc];
            *(uint4*)&As[1][r][kc] = *(const uint4*)&Alo[(size_t)(m0 + r) * 192 + k0 + kc];
        }
        // B tiles: 32 k x 128 n, 2 x 8 bf16 per thread per array
        #pragma unroll
        for (int i = 0; i < 2; i++) {
            int e  = t + i * 256;
            int kr = e >> 4;
            int nc = (e & 15) * 8;
            *(uint4*)&Bs[0][kr][nc] = *(const uint4*)&Xhi[(size_t)(k0 + kr) * HW + n0 + nc];
            *(uint4*)&Bs[1][kr][nc] = *(const uint4*)&Xlo[(size_t)(k0 + kr) * HW + n0 + nc];
        }
        __syncthreads();

        #pragma unroll
        for (int ks = 0; ks < GBK; ks += 16) {
            uint32_t afrag[2][2][4];  // [hi/lo][mi][4]
            uint32_t bfrag[2][4][2];  // [hi/lo][ni][2]
            #pragma unroll
            for (int z = 0; z < 2; z++) {
                #pragma unroll
                for (int mi = 0; mi < 2; mi++) {
                    int row = wm * 32 + mi * 16 + (lane & 15);
                    int col = ks + (lane >> 4) * 8;
                    uint32_t ad = (uint32_t)__cvta_generic_to_shared(&As[z][row][col]);
                    ldsm_x4(afrag[z][mi][0], afrag[z][mi][1], afrag[z][mi][2], afrag[z][mi][3], ad);
                }
                #pragma unroll
                for (int ni = 0; ni < 4; ni++) {
                    int kr = ks + (lane & 15);
                    int nc = wn * 32 + ni * 8;
                    uint32_t bd = (uint32_t)__cvta_generic_to_shared(&Bs[z][kr][nc]);
                    ldsm_x2t(bfrag[z][ni][0], bfrag[z][ni][1], bd);
                }
            }
            #pragma unroll
            for (int mi = 0; mi < 2; mi++)
                #pragma unroll
                for (int ni = 0; ni < 4; ni++) {
                    mma16816(acc[mi][ni], afrag[0][mi], bfrag[0][ni]);  // hi*hi
                    mma16816(acc[mi][ni], afrag[0][mi], bfrag[1][ni]);  // hi*lo
                    mma16816(acc[mi][ni], afrag[1][mi], bfrag[0][ni]);  // lo*hi
                }
        }
        __syncthreads();
    }

    // epilogue
    #pragma unroll
    for (int mi = 0; mi < 2; mi++)
        #pragma unroll
        for (int ni = 0; ni < 4; ni++) {
            int row = m0 + wm * 32 + mi * 16 + (lane >> 2);
            int col = n0 + wn * 32 + ni * 8 + 2 * (lane & 3);
            *(float2*)&Cc[(size_t)row * HW + col]       = *(float2*)&acc[mi][ni][0];
            *(float2*)&Cc[(size_t)(row + 8) * HW + col] = *(float2*)&acc[mi][ni][2];
        }
}

// ---------------- depthwise 3x3 conv + fused sumsq partials ----------------
__global__ void k_dwconv(const float* __restrict__ w)
{
    const int ch = blockIdx.y;
    const int b  = blockIdx.z;
    __shared__ float wk[9];
    if (threadIdx.x < 9) wk[threadIdx.x] = w[ch * 9 + threadIdx.x];
    __syncthreads();

    const int y = blockIdx.x;                 // one image row per block
    const int x = threadIdx.x;
    const int p = y * IMG + x;
    const float* src = g_qkv + ((size_t)b * C3 + ch) * HW;

    float s = 0.f;
    #pragma unroll
    for (int dy = -1; dy <= 1; dy++) {
        int yy = y + dy;
        if (yy < 0 || yy >= IMG) continue;
        #pragma unroll
        for (int dx = -1; dx <= 1; dx++) {
            int xx = x + dx;
            if (xx < 0 || xx >= IMG) continue;
            s += wk[(dy + 1) * 3 + (dx + 1)] * src[yy * IMG + xx];
        }
    }
    __nv_bfloat16 h = __float2bfloat16_rn(s);
    __nv_bfloat16 l = __float2bfloat16_rn(s - __bfloat162float(h));
    g_dw_hi[((size_t)b * C3 + ch) * HW + p] = h;
    g_dw_lo[((size_t)b * C3 + ch) * HW + p] = l;

    if (ch < 2 * C) {
        __shared__ float red[256];
        red[threadIdx.x] = s * s;
        __syncthreads();
        for (int st = 128; st > 0; st >>= 1) {
            if (threadIdx.x < st) red[threadIdx.x] += red[threadIdx.x + st];
            __syncthreads();
        }
        if (threadIdx.x == 0)
            g_ssq_part[((size_t)b * 2 * C + ch) * 256 + y] = red[0];
    }
}

__global__ void k_ssq_reduce()
{
    const int idx = blockIdx.x;      // 0 .. B*2C-1
    const int b  = idx / (2 * C);
    const int ch = idx % (2 * C);
    const int t  = threadIdx.x;
    __shared__ float red[256];
    red[t] = g_ssq_part[((size_t)b * 2 * C + ch) * 256 + t];
    __syncthreads();
    for (int st = 128; st > 0; st >>= 1) {
        if (t < st) red[t] += red[t + st];
        __syncthreads();
    }
    if (t == 0) g_sumsq[ch / C][b * C + ch % C] = red[0];
}

// ---------------- Gram partials (256 threads, bf16 hi/lo input) ----------------
__global__ __launch_bounds__(256) void k_gram()
{
    const int chunk = blockIdx.x;  // 0..63 (n-chunks of 1024)
    const int h     = blockIdx.y;
    const int b     = blockIdx.z;

    __shared__ float Qs[32][49];
    __shared__ float Ks[32][49];

    const size_t qoff = ((size_t)b * C3 + h * CPH) * HW + (size_t)chunk * 1024;
    const __nv_bfloat16* qh = g_dw_hi + qoff;
    const __nv_bfloat16* ql = g_dw_lo + qoff;
    const __nv_bfloat16* kh = qh + (size_t)C * HW;
    const __nv_bfloat16* kl = ql + (size_t)C * HW;

    const int t  = threadIdx.x;
    const int tx = t & 15;   // 16 cols groups of 3
    const int ty = t >> 4;   // 16 row groups of 3

    float acc[3][3];
    #pragma unroll
    for (int i = 0; i < 3; i++)
        #pragma unroll
        for (int j = 0; j < 3; j++) acc[i][j] = 0.f;

    for (int nt = 0; nt < 1024; nt += 32) {
        #pragma unroll
        for (int i = 0; i < 6; i++) {
            int e  = t + i * 256;
            int c  = e >> 5;
            int kk = e & 31;
            size_t o = (size_t)c * HW + nt + kk;
            Qs[kk][c] = __bfloat162float(qh[o]) + __bfloat162float(ql[o]);
            Ks[kk][c] = __bfloat162float(kh[o]) + __bfloat162float(kl[o]);
        }
        __syncthreads();
        #pragma unroll 8
        for (int kk = 0; kk < 32; kk++) {
            float a[3], bb[3];
            #pragma unroll
            for (int i = 0; i < 3; i++) a[i]  = Qs[kk][ty * 3 + i];
            #pragma unroll
            for (int j = 0; j < 3; j++) bb[j] = Ks[kk][tx * 3 + j];
            #pragma unroll
            for (int i = 0; i < 3; i++)
                #pragma unroll
                for (int j = 0; j < 3; j++)
                    acc[i][j] += a[i] * bb[j];
        }
        __syncthreads();
    }

    const size_t base = (((size_t)(b * NH + h)) * 64 + chunk) * (CPH * CPH);
    #pragma unroll
    for (int i = 0; i < 3; i++)
        #pragma unroll
        for (int j = 0; j < 3; j++)
            g_gram_part[base + (ty * 3 + i) * CPH + tx * 3 + j] = acc[i][j];
}

__global__ void k_gram_reduce()
{
    const int idx = blockIdx.x * blockDim.x + threadIdx.x;
    if (idx >= B * NH * CPH * CPH) return;
    const int bh = idx / (CPH * CPH);
    const int cd = idx % (CPH * CPH);
    float s = 0.f;
    for (int ck = 0; ck < 64; ck++)
        s += g_gram_part[((size_t)bh * 64 + ck) * (CPH * CPH) + cd];
    g_gram[idx] = s;
}

// ---------------- normalize + temperature + softmax over d ----------------
__global__ void k_softmax(const float* __restrict__ temperature)
{
    const int bh = blockIdx.x;
    const int b  = bh >> 2;
    const int h  = bh & 3;
    const int c  = threadIdx.x;
    if (c >= CPH) return;

    const float tv = temperature[h];
    const float nq = fmaxf(sqrtf(g_sumsq[0][b * C + h * CPH + c]), 1e-12f);

    float vals[CPH];
    float mx = -1e30f;
    #pragma unroll 4
    for (int d = 0; d < CPH; d++) {
        float nk = fmaxf(sqrtf(g_sumsq[1][b * C + h * CPH + d]), 1e-12f);
        float v  = g_gram[bh * (CPH * CPH) + c * CPH + d] / (nq * nk) * tv;
        vals[d] = v;
        mx = fmaxf(mx, v);
    }
    float sum = 0.f;
    #pragma unroll 4
    for (int d = 0; d < CPH; d++) {
        vals[d] = expf(vals[d] - mx);
        sum += vals[d];
    }
    const float inv = 1.f / sum;
    #pragma unroll 4
    for (int d = 0; d < CPH; d++)
        g_attn[bh * (CPH * CPH) + c * CPH + d] = vals[d] * inv;
}

// ---------------- M[b][o][h*48+d] = sum_cl proj_w[o][h*48+cl] * attn[b,h][cl][d] -------
__global__ void k_mixW(const float* __restrict__ proj_w)
{
    const int o  = blockIdx.x;
    const int b  = blockIdx.y;
    const int dg = threadIdx.x;
    const int h  = dg / CPH;
    const int d  = dg % CPH;
    float s = 0.f;
    #pragma unroll 8
    for (int cl = 0; cl < CPH; cl++)
        s += proj_w[o * C + h * CPH + cl] *
             g_attn[((size_t)(b * NH + h)) * (CPH * CPH) + cl * CPH + d];
    g_M[((size_t)b * C + o) * C + dg] = s;
}

// ---------------- launch ----------------
extern "C" void kernel_launch(void* const* d_in, const int* in_sizes, int n_in,
                              void* d_out, int out_size)
{
    const float* x      = (const float*)d_in[0];
    const float* qkv_w  = (const float*)d_in[1];
    const float* dw_w   = (const float*)d_in[2];
    const float* proj_w = (const float*)d_in[3];
    const float* temp   = (const float*)d_in[4];
    float* out = (float*)d_out;

    float *p_qkv, *p_M;
    __nv_bfloat16 *p_xh, *p_xl, *p_wh, *p_wl, *p_dh, *p_dl, *p_Mh, *p_Ml;
    cudaGetSymbolAddress((void**)&p_qkv, g_qkv);
    cudaGetSymbolAddress((void**)&p_M,   g_M);
    cudaGetSymbolAddress((void**)&p_xh,  g_x_hi);
    cudaGetSymbolAddress((void**)&p_xl,  g_x_lo);
    cudaGetSymbolAddress((void**)&p_wh,  g_w_hi);
    cudaGetSymbolAddress((void**)&p_wl,  g_w_lo);
    cudaGetSymbolAddress((void**)&p_dh,  g_dw_hi);
    cudaGetSymbolAddress((void**)&p_dl,  g_dw_lo);
    cudaGetSymbolAddress((void**)&p_Mh,  g_M_hi);
    cudaGetSymbolAddress((void**)&p_Ml,  g_M_lo);

    // 0) convert inputs to bf16 hi/lo
    {
        int n4 = B * C * HW / 4;
        k_cvt<<<(n4 + 255) / 256, 256>>>(x, p_xh, p_xl, n4);
        int w4 = C3 * C / 4;
        k_cvt<<<(w4 + 255) / 256, 256>>>(qkv_w, p_wh, p_wl, w4);
    }

    // 1) qkv = qkv_w @ x  (per batch [576x192]@[192x65536]) via tensor cores
    gemm_bf16<<<dim3(HW / GBN, C3 / GBM, B), 256>>>(
        p_wh, p_wl, 0, p_xh, p_xl, (size_t)C * HW, p_qkv, (size_t)C3 * HW);

    // 2) depthwise 3x3 conv (+ fused sumsq partials), bf16 hi/lo output
    k_dwconv<<<dim3(IMG, C3, B), 256>>>(dw_w);
    k_ssq_reduce<<<B * 2 * C, 256>>>();

    // 3) Gram + reduce
    k_gram<<<dim3(64, NH, B), 256>>>();
    k_gram_reduce<<<(B * NH * CPH * CPH + 255) / 256, 256>>>();

    // 4) softmax, fold proj into M, convert M
    k_softmax<<<B * NH, 64>>>(temp);
    k_mixW<<<dim3(C, B), C>>>(proj_w);
    {
        int m4 = B * C * C / 4;
        k_cvt<<<(m4 + 255) / 256, 256>>>(p_M, p_Mh, p_Ml, m4);
    }

    // 5) out = M @ v (per batch [192x192]@[192x65536]) via tensor cores
    gemm_bf16<<<dim3(HW / GBN, C / GBM, B), 256>>>(
        p_Mh, p_Ml, (size_t)C * C,
        p_dh + (size_t)2 * C * HW, p_dl + (size_t)2 * C * HW, (size_t)C3 * HW,
        out, (size_t)C * HW);
}

// round 3
// speedup vs baseline: 2.0701x; 1.0342x over previous
#include <cuda_runtime.h>
#include <cuda_bf16.h>
#include <math.h>
#include <stdint.h>

// Problem constants (fixed by setup_inputs)
#define B 4
#define C 192
#define C3 576          // 3*C
#define NH 4
#define CPH 48          // C / NH
#define HW 65536        // 256*256
#define IMG 256
#define DW_ROWS 32      // rows per dwconv block

// ---------------- device scratch (no allocs allowed) ----------------
__device__ float g_qkv[(size_t)B * C3 * HW];           // after 1x1 conv (fp32)
__device__ __nv_bfloat16 g_dw_hi[(size_t)B * C3 * HW]; // after depthwise conv, hi
__device__ __nv_bfloat16 g_dw_lo[(size_t)B * C3 * HW]; // lo
__device__ __nv_bfloat16 g_w_hi[C3 * C];
__device__ __nv_bfloat16 g_w_lo[C3 * C];
__device__ __nv_bfloat16 g_M_hi[B * C * C];
__device__ __nv_bfloat16 g_M_lo[B * C * C];
__device__ float g_ssq_part[B * 2 * C * (IMG / DW_ROWS)]; // 8 chunks per row
__device__ float g_sumsq[2][B * C];
__device__ float g_gram_part[(size_t)B * NH * 64 * CPH * CPH];
__device__ float g_gram[B * NH * CPH * CPH];
__device__ float g_attn[B * NH * CPH * CPH];
__device__ float g_M[B * C * C];

union BF4 { __nv_bfloat16 h[4]; uint2 u; };

// ---------------- fp32 -> bf16 hi/lo split (small tensors only) ----------------
__global__ void k_cvt(const float* __restrict__ src,
                      __nv_bfloat16* __restrict__ hi,
                      __nv_bfloat16* __restrict__ lo, int n4)
{
    int i = blockIdx.x * 256 + threadIdx.x;
    if (i >= n4) return;
    float4 v = ((const float4*)src)[i];
    BF4 hh, ll;
    float vv[4] = {v.x, v.y, v.z, v.w};
    #pragma unroll
    for (int j = 0; j < 4; j++) {
        hh.h[j] = __float2bfloat16_rn(vv[j]);
        ll.h[j] = __float2bfloat16_rn(vv[j] - __bfloat162float(hh.h[j]));
    }
    ((uint2*)hi)[i] = hh.u;
    ((uint2*)lo)[i] = ll.u;
}

// ---------------- HMMA helpers ----------------
__device__ __forceinline__ void ldsm_x4(uint32_t& r0, uint32_t& r1, uint32_t& r2, uint32_t& r3, uint32_t addr) {
    asm volatile("ldmatrix.sync.aligned.m8n8.x4.shared.b16 {%0,%1,%2,%3}, [%4];"
                 : "=r"(r0), "=r"(r1), "=r"(r2), "=r"(r3) : "r"(addr));
}
__device__ __forceinline__ void ldsm_x2t(uint32_t& r0, uint32_t& r1, uint32_t addr) {
    asm volatile("ldmatrix.sync.aligned.m8n8.x2.trans.shared.b16 {%0,%1}, [%2];"
                 : "=r"(r0), "=r"(r1) : "r"(addr));
}
__device__ __forceinline__ void mma16816(float* d, const uint32_t* a, const uint32_t* b) {
    asm volatile("mma.sync.aligned.m16n8k16.row.col.f32.bf16.bf16.f32 "
                 "{%0,%1,%2,%3}, {%4,%5,%6,%7}, {%8,%9}, {%0,%1,%2,%3};"
                 : "+f"(d[0]), "+f"(d[1]), "+f"(d[2]), "+f"(d[3])
                 : "r"(a[0]), "r"(a[1]), "r"(a[2]), "r"(a[3]), "r"(b[0]), "r"(b[1]));
}

#define GBM 64
#define GBN 128
#define GBK 32

// ---------------- GEMM1: A bf16 hi/lo (weights), X fp32 (converted in-kernel) ------
__global__ __launch_bounds__(256) void gemm_bf16_xf32(
    const __nv_bfloat16* __restrict__ Ahi, const __nv_bfloat16* __restrict__ Alo,
    const float* __restrict__ X, size_t xBatch,
    float* __restrict__ Cc, size_t cBatch)
{
    const int b = blockIdx.z;
    X  += (size_t)b * xBatch;
    Cc += (size_t)b * cBatch;

    const int n0 = blockIdx.x * GBN;
    const int m0 = blockIdx.y * GBM;

    __shared__ __nv_bfloat16 As[2][GBM][40];
    __shared__ __nv_bfloat16 Bs[2][GBK][136];

    const int t    = threadIdx.x;
    const int lane = t & 31;
    const int w    = t >> 5;
    const int wm   = w & 1;
    const int wn   = w >> 1;

    float acc[2][4][4];
    #pragma unroll
    for (int mi = 0; mi < 2; mi++)
        #pragma unroll
        for (int ni = 0; ni < 4; ni++)
            #pragma unroll
            for (int r = 0; r < 4; r++) acc[mi][ni][r] = 0.f;

    for (int k0 = 0; k0 < 192; k0 += GBK) {
        {
            int r  = t >> 2;
            int kc = (t & 3) * 8;
            *(uint4*)&As[0][r][kc] = *(const uint4*)&Ahi[(size_t)(m0 + r) * 192 + k0 + kc];
            *(uint4*)&As[1][r][kc] = *(const uint4*)&Alo[(size_t)(m0 + r) * 192 + k0 + kc];
        }
        // B tile: 32 k x 128 n fp32 -> split to hi/lo in regs
        #pragma unroll
        for (int i = 0; i < 4; i++) {
            int e  = t + i * 256;       // 0..1023 float4s
            int kr = e >> 5;            // k 0..31
            int nc = (e & 31) * 4;      // n offset
            float4 v = *(const float4*)&X[(size_t)(k0 + kr) * HW + n0 + nc];
            BF4 hh, ll;
            float vv[4] = {v.x, v.y, v.z, v.w};
            #pragma unroll
            for (int j = 0; j < 4; j++) {
                hh.h[j] = __float2bfloat16_rn(vv[j]);
                ll.h[j] = __float2bfloat16_rn(vv[j] - __bfloat162float(hh.h[j]));
            }
            *(uint2*)&Bs[0][kr][nc] = hh.u;
            *(uint2*)&Bs[1][kr][nc] = ll.u;
        }
        __syncthreads();

        #pragma unroll
        for (int ks = 0; ks < GBK; ks += 16) {
            uint32_t afrag[2][2][4];
            uint32_t bfrag[2][4][2];
            #pragma unroll
            for (int z = 0; z < 2; z++) {
                #pragma unroll
                for (int mi = 0; mi < 2; mi++) {
                    int row = wm * 32 + mi * 16 + (lane & 15);
                    int col = ks + (lane >> 4) * 8;
                    uint32_t ad = (uint32_t)__cvta_generic_to_shared(&As[z][row][col]);
                    ldsm_x4(afrag[z][mi][0], afrag[z][mi][1], afrag[z][mi][2], afrag[z][mi][3], ad);
                }
                #pragma unroll
                for (int ni = 0; ni < 4; ni++) {
                    int kr = ks + (lane & 15);
                    int nc = wn * 32 + ni * 8;
                    uint32_t bd = (uint32_t)__cvta_generic_to_shared(&Bs[z][kr][nc]);
                    ldsm_x2t(bfrag[z][ni][0], bfrag[z][ni][1], bd);
                }
            }
            #pragma unroll
            for (int mi = 0; mi < 2; mi++)
                #pragma unroll
                for (int ni = 0; ni < 4; ni++) {
                    mma16816(acc[mi][ni], afrag[0][mi], bfrag[0][ni]);
                    mma16816(acc[mi][ni], afrag[0][mi], bfrag[1][ni]);
                    mma16816(acc[mi][ni], afrag[1][mi], bfrag[0][ni]);
                }
        }
        __syncthreads();
    }

    #pragma unroll
    for (int mi = 0; mi < 2; mi++)
        #pragma unroll
        for (int ni = 0; ni < 4; ni++) {
            int row = m0 + wm * 32 + mi * 16 + (lane >> 2);
            int col = n0 + wn * 32 + ni * 8 + 2 * (lane & 3);
            *(float2*)&Cc[(size_t)row * HW + col]       = *(float2*)&acc[mi][ni][0];
            *(float2*)&Cc[(size_t)(row + 8) * HW + col] = *(float2*)&acc[mi][ni][2];
        }
}

// ---------------- GEMM2: both operands bf16 hi/lo ----------------
__global__ __launch_bounds__(256) void gemm_bf16(
    const __nv_bfloat16* __restrict__ Ahi, const __nv_bfloat16* __restrict__ Alo, size_t aBatch,
    const __nv_bfloat16* __restrict__ Xhi, const __nv_bfloat16* __restrict__ Xlo, size_t xBatch,
    float* __restrict__ Cc, size_t cBatch)
{
    const int b = blockIdx.z;
    Ahi += (size_t)b * aBatch;  Alo += (size_t)b * aBatch;
    Xhi += (size_t)b * xBatch;  Xlo += (size_t)b * xBatch;
    Cc  += (size_t)b * cBatch;

    const int n0 = blockIdx.x * GBN;
    const int m0 = blockIdx.y * GBM;

    __shared__ __nv_bfloat16 As[2][GBM][40];
    __shared__ __nv_bfloat16 Bs[2][GBK][136];

    const int t    = threadIdx.x;
    const int lane = t & 31;
    const int w    = t >> 5;
    const int wm   = w & 1;
    const int wn   = w >> 1;

    float acc[2][4][4];
    #pragma unroll
    for (int mi = 0; mi < 2; mi++)
        #pragma unroll
        for (int ni = 0; ni < 4; ni++)
            #pragma unroll
            for (int r = 0; r < 4; r++) acc[mi][ni][r] = 0.f;

    for (int k0 = 0; k0 < 192; k0 += GBK) {
        {
            int r  = t >> 2;
            int kc = (t & 3) * 8;
            *(uint4*)&As[0][r][kc] = *(const uint4*)&Ahi[(size_t)(m0 + r) * 192 + k0 + kc];
            *(uint4*)&As[1][r][kc] = *(const uint4*)&Alo[(size_t)(m0 + r) * 192 + k0 + kc];
        }
        #pragma unroll
        for (int i = 0; i < 2; i++) {
            int e  = t + i * 256;
            int kr = e >> 4;
            int nc = (e & 15) * 8;
            *(uint4*)&Bs[0][kr][nc] = *(const uint4*)&Xhi[(size_t)(k0 + kr) * HW + n0 + nc];
            *(uint4*)&Bs[1][kr][nc] = *(const uint4*)&Xlo[(size_t)(k0 + kr) * HW + n0 + nc];
        }
        __syncthreads();

        #pragma unroll
        for (int ks = 0; ks < GBK; ks += 16) {
            uint32_t afrag[2][2][4];
            uint32_t bfrag[2][4][2];
            #pragma unroll
            for (int z = 0; z < 2; z++) {
                #pragma unroll
                for (int mi = 0; mi < 2; mi++) {
                    int row = wm * 32 + mi * 16 + (lane & 15);
                    int col = ks + (lane >> 4) * 8;
                    uint32_t ad = (uint32_t)__cvta_generic_to_shared(&As[z][row][col]);
                    ldsm_x4(afrag[z][mi][0], afrag[z][mi][1], afrag[z][mi][2], afrag[z][mi][3], ad);
                }
                #pragma unroll
                for (int ni = 0; ni < 4; ni++) {
                    int kr = ks + (lane & 15);
                    int nc = wn * 32 + ni * 8;
                    uint32_t bd = (uint32_t)__cvta_generic_to_shared(&Bs[z][kr][nc]);
                    ldsm_x2t(bfrag[z][ni][0], bfrag[z][ni][1], bd);
                }
            }
            #pragma unroll
            for (int mi = 0; mi < 2; mi++)
                #pragma unroll
                for (int ni = 0; ni < 4; ni++) {
                    mma16816(acc[mi][ni], afrag[0][mi], bfrag[0][ni]);
                    mma16816(acc[mi][ni], afrag[0][mi], bfrag[1][ni]);
                    mma16816(acc[mi][ni], afrag[1][mi], bfrag[0][ni]);
                }
        }
        __syncthreads();
    }

    #pragma unroll
    for (int mi = 0; mi < 2; mi++)
        #pragma unroll
        for (int ni = 0; ni < 4; ni++) {
            int row = m0 + wm * 32 + mi * 16 + (lane >> 2);
            int col = n0 + wn * 32 + ni * 8 + 2 * (lane & 3);
            *(float2*)&Cc[(size_t)row * HW + col]       = *(float2*)&acc[mi][ni][0];
            *(float2*)&Cc[(size_t)(row + 8) * HW + col] = *(float2*)&acc[mi][ni][2];
        }
}

// ---------------- tiled depthwise 3x3 conv + fused sumsq ----------------
// Block: one (b, ch, 32-row band). 256 threads = one column each.
__global__ __launch_bounds__(256) void k_dwconv(const float* __restrict__ w)
{
    const int ch = blockIdx.y;
    const int b  = blockIdx.z;
    const int y0 = blockIdx.x * DW_ROWS;
    const int t  = threadIdx.x;

    __shared__ float tile[DW_ROWS + 2][IMG + 2];

    float w0 = __ldg(&w[ch * 9 + 0]), w1 = __ldg(&w[ch * 9 + 1]), w2 = __ldg(&w[ch * 9 + 2]);
    float w3 = __ldg(&w[ch * 9 + 3]), w4 = __ldg(&w[ch * 9 + 4]), w5 = __ldg(&w[ch * 9 + 5]);
    float w6 = __ldg(&w[ch * 9 + 6]), w7 = __ldg(&w[ch * 9 + 7]), w8 = __ldg(&w[ch * 9 + 8]);

    const float* src = g_qkv + ((size_t)b * C3 + ch) * HW;

    #pragma unroll 4
    for (int r = 0; r < DW_ROWS + 2; r++) {
        int y = y0 + r - 1;
        tile[r][t + 1] = (y >= 0 && y < IMG) ? src[y * IMG + t] : 0.f;
        if (t < 2) tile[r][t * (IMG + 1)] = 0.f;   // zero halo columns (x=-1, x=256)
    }
    __syncthreads();

    __nv_bfloat16* hi = g_dw_hi + ((size_t)b * C3 + ch) * HW;
    __nv_bfloat16* lo = g_dw_lo + ((size_t)b * C3 + ch) * HW;

    float a0 = tile[0][t], a1 = tile[0][t + 1], a2 = tile[0][t + 2];
    float b0 = tile[1][t], b1 = tile[1][t + 1], b2 = tile[1][t + 2];
    float ssq = 0.f;

    #pragma unroll 8
    for (int r = 0; r < DW_ROWS; r++) {
        float c0 = tile[r + 2][t], c1 = tile[r + 2][t + 1], c2 = tile[r + 2][t + 2];
        float s = w0 * a0 + w1 * a1 + w2 * a2
                + w3 * b0 + w4 * b1 + w5 * b2
                + w6 * c0 + w7 * c1 + w8 * c2;
        int p = (y0 + r) * IMG + t;
        __nv_bfloat16 h = __float2bfloat16_rn(s);
        hi[p] = h;
        lo[p] = __float2bfloat16_rn(s - __bfloat162float(h));
        ssq += s * s;
        a0 = b0; a1 = b1; a2 = b2;
        b0 = c0; b1 = c1; b2 = c2;
    }

    if (ch < 2 * C) {
        #pragma unroll
        for (int st = 16; st > 0; st >>= 1)
            ssq += __shfl_xor_sync(0xffffffffu, ssq, st);
        __shared__ float wred[8];
        if ((t & 31) == 0) wred[t >> 5] = ssq;
        __syncthreads();
        if (t == 0) {
            float s = 0.f;
            #pragma unroll
            for (int i = 0; i < 8; i++) s += wred[i];
            g_ssq_part[((size_t)b * 2 * C + ch) * (IMG / DW_ROWS) + blockIdx.x] = s;
        }
    }
}

__global__ void k_ssq_reduce()
{
    const int idx = blockIdx.x * blockDim.x + threadIdx.x;
    if (idx >= B * 2 * C) return;
    float s = 0.f;
    #pragma unroll
    for (int i = 0; i < IMG / DW_ROWS; i++)
        s += g_ssq_part[(size_t)idx * (IMG / DW_ROWS) + i];
    const int b  = idx / (2 * C);
    const int ch = idx % (2 * C);
    g_sumsq[ch / C][b * C + ch % C] = s;
}

// ---------------- Gram partials (bf16 hi/lo, uint2 loads, 64-wide n steps) --------
__global__ __launch_bounds__(256) void k_gram()
{
    const int chunk = blockIdx.x;  // 0..63 (n-chunks of 1024)
    const int h     = blockIdx.y;
    const int b     = blockIdx.z;

    __shared__ float Qs[64][49];
    __shared__ float Ks[64][49];

    const size_t qoff = ((size_t)b * C3 + h * CPH) * HW + (size_t)chunk * 1024;
    const __nv_bfloat16* qh = g_dw_hi + qoff;
    const __nv_bfloat16* ql = g_dw_lo + qoff;
    const __nv_bfloat16* kh = qh + (size_t)C * HW;
    const __nv_bfloat16* kl = ql + (size_t)C * HW;

    const int t  = threadIdx.x;
    const int tx = t & 15;
    const int ty = t >> 4;

    float acc[3][3];
    #pragma unroll
    for (int i = 0; i < 3; i++)
        #pragma unroll
        for (int j = 0; j < 3; j++) acc[i][j] = 0.f;

    for (int nt = 0; nt < 1024; nt += 64) {
        #pragma unroll
        for (int i = 0; i < 3; i++) {
            int e   = t + i * 256;       // 0..767
            int row = e >> 4;            // 0..47
            int c4  = (e & 15) * 4;      // 0..60
            size_t o = (size_t)row * HW + nt + c4;
            BF4 vh, vl;
            vh.u = *(const uint2*)&qh[o];
            vl.u = *(const uint2*)&ql[o];
            #pragma unroll
            for (int j = 0; j < 4; j++)
                Qs[c4 + j][row] = __bfloat162float(vh.h[j]) + __bfloat162float(vl.h[j]);
            vh.u = *(const uint2*)&kh[o];
            vl.u = *(const uint2*)&kl[o];
            #pragma unroll
            for (int j = 0; j < 4; j++)
                Ks[c4 + j][row] = __bfloat162float(vh.h[j]) + __bfloat162float(vl.h[j]);
        }
        __syncthreads();
        #pragma unroll 8
        for (int kk = 0; kk < 64; kk++) {
            float a[3], bb[3];
            #pragma unroll
            for (int i = 0; i < 3; i++) a[i]  = Qs[kk][ty * 3 + i];
            #pragma unroll
            for (int j = 0; j < 3; j++) bb[j] = Ks[kk][tx * 3 + j];
            #pragma unroll
            for (int i = 0; i < 3; i++)
                #pragma unroll
                for (int j = 0; j < 3; j++)
                    acc[i][j] += a[i] * bb[j];
        }
        __syncthreads();
    }

    const size_t base = (((size_t)(b * NH + h)) * 64 + chunk) * (CPH * CPH);
    #pragma unroll
    for (int i = 0; i < 3; i++)
        #pragma unroll
        for (int j = 0; j < 3; j++)
            g_gram_part[base + (ty * 3 + i) * CPH + tx * 3 + j] = acc[i][j];
}

__global__ void k_gram_reduce()
{
    const int idx = blockIdx.x * blockDim.x + threadIdx.x;
    if (idx >= B * NH * CPH * CPH) return;
    const int bh = idx / (CPH * CPH);
    const int cd = idx % (CPH * CPH);
    float s = 0.f;
    for (int ck = 0; ck < 64; ck++)
        s += g_gram_part[((size_t)bh * 64 + ck) * (CPH * CPH) + cd];
    g_gram[idx] = s;
}

// ---------------- normalize + temperature + softmax over d ----------------
__global__ void k_softmax(const float* __restrict__ temperature)
{
    const int bh = blockIdx.x;
    const int b  = bh >> 2;
    const int h  = bh & 3;
    const int c  = threadIdx.x;
    if (c >= CPH) return;

    const float tv = temperature[h];
    const float nq = fmaxf(sqrtf(g_sumsq[0][b * C + h * CPH + c]), 1e-12f);

    float vals[CPH];
    float mx = -1e30f;
    #pragma unroll 4
    for (int d = 0; d < CPH; d++) {
        float nk = fmaxf(sqrtf(g_sumsq[1][b * C + h * CPH + d]), 1e-12f);
        float v  = g_gram[bh * (CPH * CPH) + c * CPH + d] / (nq * nk) * tv;
        vals[d] = v;
        mx = fmaxf(mx, v);
    }
    float sum = 0.f;
    #pragma unroll 4
    for (int d = 0; d < CPH; d++) {
        vals[d] = expf(vals[d] - mx);
        sum += vals[d];
    }
    const float inv = 1.f / sum;
    #pragma unroll 4
    for (int d = 0; d < CPH; d++)
        g_attn[bh * (CPH * CPH) + c * CPH + d] = vals[d] * inv;
}

// ---------------- M = proj @ blockdiag(attn) ----------------
__global__ void k_mixW(const float* __restrict__ proj_w)
{
    const int o  = blockIdx.x;
    const int b  = blockIdx.y;
    const int dg = threadIdx.x;
    const int h  = dg / CPH;
    const int d  = dg % CPH;
    float s = 0.f;
    #pragma unroll 8
    for (int cl = 0; cl < CPH; cl++)
        s += proj_w[o * C + h * CPH + cl] *
             g_attn[((size_t)(b * NH + h)) * (CPH * CPH) + cl * CPH + d];
    g_M[((size_t)b * C + o) * C + dg] = s;
}

// ---------------- launch ----------------
extern "C" void kernel_launch(void* const* d_in, const int* in_sizes, int n_in,
                              void* d_out, int out_size)
{
    const float* x      = (const float*)d_in[0];
    const float* qkv_w  = (const float*)d_in[1];
    const float* dw_w   = (const float*)d_in[2];
    const float* proj_w = (const float*)d_in[3];
    const float* temp   = (const float*)d_in[4];
    float* out = (float*)d_out;

    float *p_qkv, *p_M;
    __nv_bfloat16 *p_wh, *p_wl, *p_dh, *p_dl, *p_Mh, *p_Ml;
    cudaGetSymbolAddress((void**)&p_qkv, g_qkv);
    cudaGetSymbolAddress((void**)&p_M,   g_M);
    cudaGetSymbolAddress((void**)&p_wh,  g_w_hi);
    cudaGetSymbolAddress((void**)&p_wl,  g_w_lo);
    cudaGetSymbolAddress((void**)&p_dh,  g_dw_hi);
    cudaGetSymbolAddress((void**)&p_dl,  g_dw_lo);
    cudaGetSymbolAddress((void**)&p_Mh,  g_M_hi);
    cudaGetSymbolAddress((void**)&p_Ml,  g_M_lo);

    // 0) split weights to bf16 hi/lo (tiny)
    {
        int w4 = C3 * C / 4;
        k_cvt<<<(w4 + 255) / 256, 256>>>(qkv_w, p_wh, p_wl, w4);
    }

    // 1) qkv = qkv_w @ x (x converted in-kernel)
    gemm_bf16_xf32<<<dim3(HW / GBN, C3 / GBM, B), 256>>>(
        p_wh, p_wl, x, (size_t)C * HW, p_qkv, (size_t)C3 * HW);

    // 2) depthwise 3x3 conv + fused sumsq partials
    k_dwconv<<<dim3(IMG / DW_ROWS, C3, B), 256>>>(dw_w);
    k_ssq_reduce<<<(B * 2 * C + 255) / 256, 256>>>();

    // 3) Gram + reduce
    k_gram<<<dim3(64, NH, B), 256>>>();
    k_gram_reduce<<<(B * NH * CPH * CPH + 255) / 256, 256>>>();

    // 4) softmax, fold proj into M, split M
    k_softmax<<<B * NH, 64>>>(temp);
    k_mixW<<<dim3(C, B), C>>>(proj_w);
    {
        int m4 = B * C * C / 4;
        k_cvt<<<(m4 + 255) / 256, 256>>>(p_M, p_Mh, p_Ml, m4);
    }

    // 5) out = M @ v
    gemm_bf16<<<dim3(HW / GBN, C / GBM, B), 256>>>(
        p_Mh, p_Ml, (size_t)C * C,
        p_dh + (size_t)2 * C * HW, p_dl + (size_t)2 * C * HW, (size_t)C3 * HW,
        out, (size_t)C * HW);
}

// round 5
// speedup vs baseline: 3.0255x; 1.4615x over previous
#include <cuda_runtime.h>
#include <cuda_bf16.h>
#include <math.h>
#include <stdint.h>

// Problem constants
#define B 4
#define C 192
#define C3 576
#define NH 4
#define CPH 48
#define HW 65536
#define IMG 256
#define DW_ROWS 32

// ---------------- device scratch ----------------
__device__ float g_qkv[(size_t)B * C3 * HW];
__device__ __nv_bfloat16 g_dw_hi[(size_t)B * C3 * HW];
__device__ __nv_bfloat16 g_dw_lo[(size_t)B * C3 * HW];
__device__ __nv_bfloat16 g_x_hi[(size_t)B * C * HW];
__device__ __nv_bfloat16 g_x_lo[(size_t)B * C * HW];
__device__ __nv_bfloat16 g_w_hi[C3 * C];
__device__ __nv_bfloat16 g_w_lo[C3 * C];
__device__ __nv_bfloat16 g_M_hi[B * C * C];
__device__ __nv_bfloat16 g_M_lo[B * C * C];
__device__ float g_ssq_part[B * 2 * C * (IMG / DW_ROWS)];
__device__ float g_sumsq[2][B * C];
__device__ float g_gram_part[(size_t)B * NH * 64 * CPH * CPH];
__device__ float g_gram[B * NH * CPH * CPH];
__device__ float g_attn[B * NH * CPH * CPH];
__device__ float g_M[B * C * C];

union BF4 { __nv_bfloat16 h[4]; uint2 u; };

// ---------------- fp32 -> bf16 hi/lo split ----------------
__global__ void k_cvt(const float* __restrict__ src,
                      __nv_bfloat16* __restrict__ hi,
                      __nv_bfloat16* __restrict__ lo, int n4)
{
    int i = blockIdx.x * 256 + threadIdx.x;
    if (i >= n4) return;
    float4 v = ((const float4*)src)[i];
    BF4 hh, ll;
    float vv[4] = {v.x, v.y, v.z, v.w};
    #pragma unroll
    for (int j = 0; j < 4; j++) {
        hh.h[j] = __float2bfloat16_rn(vv[j]);
        ll.h[j] = __float2bfloat16_rn(vv[j] - __bfloat162float(hh.h[j]));
    }
    ((uint2*)hi)[i] = hh.u;
    ((uint2*)lo)[i] = ll.u;
}

// ---------------- HMMA helpers ----------------
__device__ __forceinline__ void ldsm_x4(uint32_t& r0, uint32_t& r1, uint32_t& r2, uint32_t& r3, uint32_t addr) {
    asm volatile("ldmatrix.sync.aligned.m8n8.x4.shared.b16 {%0,%1,%2,%3}, [%4];"
                 : "=r"(r0), "=r"(r1), "=r"(r2), "=r"(r3) : "r"(addr));
}
__device__ __forceinline__ void ldsm_x2t(uint32_t& r0, uint32_t& r1, uint32_t addr) {
    asm volatile("ldmatrix.sync.aligned.m8n8.x2.trans.shared.b16 {%0,%1}, [%2];"
                 : "=r"(r0), "=r"(r1) : "r"(addr));
}
__device__ __forceinline__ void mma16816(float* d, const uint32_t* a, const uint32_t* b) {
    asm volatile("mma.sync.aligned.m16n8k16.row.col.f32.bf16.bf16.f32 "
                 "{%0,%1,%2,%3}, {%4,%5,%6,%7}, {%8,%9}, {%0,%1,%2,%3};"
                 : "+f"(d[0]), "+f"(d[1]), "+f"(d[2]), "+f"(d[3])
                 : "r"(a[0]), "r"(a[1]), "r"(a[2]), "r"(a[3]), "r"(b[0]), "r"(b[1]));
}
__device__ __forceinline__ void cp16(uint32_t saddr, const void* gptr) {
    asm volatile("cp.async.cg.shared.global [%0], [%1], 16;" :: "r"(saddr), "l"(gptr));
}
__device__ __forceinline__ uint32_t cvta_s(const void* p) {
    return (uint32_t)__cvta_generic_to_shared(p);
}

// Pipelined bf16-split GEMM.
// C[b][m][n] = sum_k (Ahi+Alo)[m][k]*(Xhi+Xlo)[k][n], K=192, N=HW.
// BM=64, BN=256, BK=32, 256 threads = 8 warps (2m x 4n), warp tile 32x64.
#define GBM 64
#define GBN 256
#define GBK 32
// smem element offsets
#define AS_STRIDE 40
#define BS_STRIDE 264
#define AS_Z   (GBM * AS_STRIDE)                 // 2560
#define AS_ST  (2 * AS_Z)                        // 5120
#define BS_Z   (GBK * BS_STRIDE)                 // 8448
#define BS_ST  (2 * BS_Z)                        // 16896
#define BS_BASE (2 * AS_ST)                      // 10240 elements
#define GSMEM_BYTES ((BS_BASE + 2 * BS_ST) * 2)  // 88064 bytes

__global__ __launch_bounds__(256) void gemm_bf16_pipe(
    const __nv_bfloat16* __restrict__ Ahi, const __nv_bfloat16* __restrict__ Alo, size_t aBatch,
    const __nv_bfloat16* __restrict__ Xhi, const __nv_bfloat16* __restrict__ Xlo, size_t xBatch,
    float* __restrict__ Cc, size_t cBatch)
{
    extern __shared__ __nv_bfloat16 smem[];
    const int b = blockIdx.z;
    Ahi += (size_t)b * aBatch;  Alo += (size_t)b * aBatch;
    Xhi += (size_t)b * xBatch;  Xlo += (size_t)b * xBatch;
    Cc  += (size_t)b * cBatch;

    const int n0 = blockIdx.x * GBN;
    const int m0 = blockIdx.y * GBM;

    const int t    = threadIdx.x;
    const int lane = t & 31;
    const int w    = t >> 5;
    const int wm   = w & 1;     // 0..1
    const int wn   = w >> 1;    // 0..3

    // A load mapping: row=t>>2 (0..63), kq=(t&3)*8
    const int arow = t >> 2;
    const int akq  = (t & 3) * 8;

    float acc[2][8][4];
    #pragma unroll
    for (int mi = 0; mi < 2; mi++)
        #pragma unroll
        for (int ni = 0; ni < 8; ni++)
            #pragma unroll
            for (int r = 0; r < 4; r++) acc[mi][ni][r] = 0.f;

    // ---- async load helpers ----
    auto loadStage = [&](int st, int k0) {
        // A: 64 rows x 32 k, hi and lo
        cp16(cvta_s(&smem[st * AS_ST + 0 * AS_Z + arow * AS_STRIDE + akq]),
             &Ahi[(size_t)(m0 + arow) * 192 + k0 + akq]);
        cp16(cvta_s(&smem[st * AS_ST + 1 * AS_Z + arow * AS_STRIDE + akq]),
             &Alo[(size_t)(m0 + arow) * 192 + k0 + akq]);
        // B: 32 k x 256 n, hi and lo
        #pragma unroll
        for (int i = 0; i < 4; i++) {
            int e  = t + i * 256;
            int kr = e >> 5;
            int nc = (e & 31) * 8;
            const size_t gsrc = (size_t)(k0 + kr) * HW + n0 + nc;
            cp16(cvta_s(&smem[BS_BASE + st * BS_ST + 0 * BS_Z + kr * BS_STRIDE + nc]), &Xhi[gsrc]);
            cp16(cvta_s(&smem[BS_BASE + st * BS_ST + 1 * BS_Z + kr * BS_STRIDE + nc]), &Xlo[gsrc]);
        }
    };

    loadStage(0, 0);
    asm volatile("cp.async.commit_group;");

    #pragma unroll
    for (int it = 0; it < 6; it++) {
        const int st = it & 1;
        if (it < 5) {
            loadStage(st ^ 1, (it + 1) * GBK);
            asm volatile("cp.async.commit_group;");
            asm volatile("cp.async.wait_group 1;");
        } else {
            asm volatile("cp.async.wait_group 0;");
        }
        __syncthreads();

        const __nv_bfloat16* As = &smem[st * AS_ST];
        const __nv_bfloat16* Bs = &smem[BS_BASE + st * BS_ST];

        #pragma unroll
        for (int ks = 0; ks < GBK; ks += 16) {
            uint32_t afrag[2][2][4];   // [z][mi]
            uint32_t bfrag[2][8][2];   // [z][ni]
            #pragma unroll
            for (int z = 0; z < 2; z++) {
                #pragma unroll
                for (int mi = 0; mi < 2; mi++) {
                    int row = wm * 32 + mi * 16 + (lane & 15);
                    int col = ks + (lane >> 4) * 8;
                    ldsm_x4(afrag[z][mi][0], afrag[z][mi][1], afrag[z][mi][2], afrag[z][mi][3],
                            cvta_s(&As[z * AS_Z + row * AS_STRIDE + col]));
                }
                #pragma unroll
                for (int ni = 0; ni < 8; ni++) {
                    int kr = ks + (lane & 15);
                    int nc = wn * 64 + ni * 8;
                    ldsm_x2t(bfrag[z][ni][0], bfrag[z][ni][1],
                             cvta_s(&Bs[z * BS_Z + kr * BS_STRIDE + nc]));
                }
            }
            #pragma unroll
            for (int mi = 0; mi < 2; mi++)
                #pragma unroll
                for (int ni = 0; ni < 8; ni++) {
                    mma16816(acc[mi][ni], afrag[0][mi], bfrag[0][ni]);  // hi*hi
                    mma16816(acc[mi][ni], afrag[0][mi], bfrag[1][ni]);  // hi*lo
                    mma16816(acc[mi][ni], afrag[1][mi], bfrag[0][ni]);  // lo*hi
                }
        }
        __syncthreads();
    }

    #pragma unroll
    for (int mi = 0; mi < 2; mi++)
        #pragma unroll
        for (int ni = 0; ni < 8; ni++) {
            int row = m0 + wm * 32 + mi * 16 + (lane >> 2);
            int col = n0 + wn * 64 + ni * 8 + 2 * (lane & 3);
            *(float2*)&Cc[(size_t)row * HW + col]       = *(float2*)&acc[mi][ni][0];
            *(float2*)&Cc[(size_t)(row + 8) * HW + col] = *(float2*)&acc[mi][ni][2];
        }
}

// ---------------- tiled depthwise 3x3 conv + fused sumsq ----------------
__global__ __launch_bounds__(256) void k_dwconv(const float* __restrict__ w)
{
    const int ch = blockIdx.y;
    const int b  = blockIdx.z;
    const int y0 = blockIdx.x * DW_ROWS;
    const int t  = threadIdx.x;

    __shared__ float tile[DW_ROWS + 2][IMG + 2];

    float w0 = __ldg(&w[ch * 9 + 0]), w1 = __ldg(&w[ch * 9 + 1]), w2 = __ldg(&w[ch * 9 + 2]);
    float w3 = __ldg(&w[ch * 9 + 3]), w4 = __ldg(&w[ch * 9 + 4]), w5 = __ldg(&w[ch * 9 + 5]);
    float w6 = __ldg(&w[ch * 9 + 6]), w7 = __ldg(&w[ch * 9 + 7]), w8 = __ldg(&w[ch * 9 + 8]);

    const float* src = g_qkv + ((size_t)b * C3 + ch) * HW;

    #pragma unroll 4
    for (int r = 0; r < DW_ROWS + 2; r++) {
        int y = y0 + r - 1;
        tile[r][t + 1] = (y >= 0 && y < IMG) ? src[y * IMG + t] : 0.f;
        if (t < 2) tile[r][t * (IMG + 1)] = 0.f;
    }
    __syncthreads();

    __nv_bfloat16* hi = g_dw_hi + ((size_t)b * C3 + ch) * HW;
    __nv_bfloat16* lo = g_dw_lo + ((size_t)b * C3 + ch) * HW;

    float a0 = tile[0][t], a1 = tile[0][t + 1], a2 = tile[0][t + 2];
    float b0 = tile[1][t], b1 = tile[1][t + 1], b2 = tile[1][t + 2];
    float ssq = 0.f;

    #pragma unroll 8
    for (int r = 0; r < DW_ROWS; r++) {
        float c0 = tile[r + 2][t], c1 = tile[r + 2][t + 1], c2 = tile[r + 2][t + 2];
        float s = w0 * a0 + w1 * a1 + w2 * a2
                + w3 * b0 + w4 * b1 + w5 * b2
                + w6 * c0 + w7 * c1 + w8 * c2;
        int p = (y0 + r) * IMG + t;
        __nv_bfloat16 h = __float2bfloat16_rn(s);
        hi[p] = h;
        lo[p] = __float2bfloat16_rn(s - __bfloat162float(h));
        ssq += s * s;
        a0 = b0; a1 = b1; a2 = b2;
        b0 = c0; b1 = c1; b2 = c2;
    }

    if (ch < 2 * C) {
        #pragma unroll
        for (int st = 16; st > 0; st >>= 1)
            ssq += __shfl_xor_sync(0xffffffffu, ssq, st);
        __shared__ float wred[8];
        if ((t & 31) == 0) wred[t >> 5] = ssq;
        __syncthreads();
        if (t == 0) {
            float s = 0.f;
            #pragma unroll
            for (int i = 0; i < 8; i++) s += wred[i];
            g_ssq_part[((size_t)b * 2 * C + ch) * (IMG / DW_ROWS) + blockIdx.x] = s;
        }
    }
}

__global__ void k_ssq_reduce()
{
    const int idx = blockIdx.x * blockDim.x + threadIdx.x;
    if (idx >= B * 2 * C) return;
    float s = 0.f;
    #pragma unroll
    for (int i = 0; i < IMG / DW_ROWS; i++)
        s += g_ssq_part[(size_t)idx * (IMG / DW_ROWS) + i];
    const int b  = idx / (2 * C);
    const int ch = idx % (2 * C);
    g_sumsq[ch / C][b * C + ch % C] = s;
}

// ---------------- Gram partials ----------------
__global__ __launch_bounds__(256) void k_gram()
{
    const int chunk = blockIdx.x;
    const int h     = blockIdx.y;
    const int b     = blockIdx.z;

    __shared__ float Qs[64][49];
    __shared__ float Ks[64][49];

    const size_t qoff = ((size_t)b * C3 + h * CPH) * HW + (size_t)chunk * 1024;
    const __nv_bfloat16* qh = g_dw_hi + qoff;
    const __nv_bfloat16* ql = g_dw_lo + qoff;
    const __nv_bfloat16* kh = qh + (size_t)C * HW;
    const __nv_bfloat16* kl = ql + (size_t)C * HW;

    const int t  = threadIdx.x;
    const int tx = t & 15;
    const int ty = t >> 4;

    float acc[3][3];
    #pragma unroll
    for (int i = 0; i < 3; i++)
        #pragma unroll
        for (int j = 0; j < 3; j++) acc[i][j] = 0.f;

    for (int nt = 0; nt < 1024; nt += 64) {
        #pragma unroll
        for (int i = 0; i < 3; i++) {
            int e   = t + i * 256;
            int row = e >> 4;
            int c4  = (e & 15) * 4;
            size_t o = (size_t)row * HW + nt + c4;
            BF4 vh, vl;
            vh.u = *(const uint2*)&qh[o];
            vl.u = *(const uint2*)&ql[o];
            #pragma unroll
            for (int j = 0; j < 4; j++)
                Qs[c4 + j][row] = __bfloat162float(vh.h[j]) + __bfloat162float(vl.h[j]);
            vh.u = *(const uint2*)&kh[o];
            vl.u = *(const uint2*)&kl[o];
            #pragma unroll
            for (int j = 0; j < 4; j++)
                Ks[c4 + j][row] = __bfloat162float(vh.h[j]) + __bfloat162float(vl.h[j]);
        }
        __syncthreads();
        #pragma unroll 8
        for (int kk = 0; kk < 64; kk++) {
            float a[3], bb[3];
            #pragma unroll
            for (int i = 0; i < 3; i++) a[i]  = Qs[kk][ty * 3 + i];
            #pragma unroll
            for (int j = 0; j < 3; j++) bb[j] = Ks[kk][tx * 3 + j];
            #pragma unroll
            for (int i = 0; i < 3; i++)
                #pragma unroll
                for (int j = 0; j < 3; j++)
                    acc[i][j] += a[i] * bb[j];
        }
        __syncthreads();
    }

    const size_t base = (((size_t)(b * NH + h)) * 64 + chunk) * (CPH * CPH);
    #pragma unroll
    for (int i = 0; i < 3; i++)
        #pragma unroll
        for (int j = 0; j < 3; j++)
            g_gram_part[base + (ty * 3 + i) * CPH + tx * 3 + j] = acc[i][j];
}

__global__ void k_gram_reduce()
{
    const int idx = blockIdx.x * blockDim.x + threadIdx.x;
    if (idx >= B * NH * CPH * CPH) return;
    const int bh = idx / (CPH * CPH);
    const int cd = idx % (CPH * CPH);
    float s = 0.f;
    for (int ck = 0; ck < 64; ck++)
        s += g_gram_part[((size_t)bh * 64 + ck) * (CPH * CPH) + cd];
    g_gram[idx] = s;
}

// ---------------- softmax ----------------
__global__ void k_softmax(const float* __restrict__ temperature)
{
    const int bh = blockIdx.x;
    const int b  = bh >> 2;
    const int h  = bh & 3;
    const int c  = threadIdx.x;
    if (c >= CPH) return;

    const float tv = temperature[h];
    const float nq = fmaxf(sqrtf(g_sumsq[0][b * C + h * CPH + c]), 1e-12f);

    float vals[CPH];
    float mx = -1e30f;
    #pragma unroll 4
    for (int d = 0; d < CPH; d++) {
        float nk = fmaxf(sqrtf(g_sumsq[1][b * C + h * CPH + d]), 1e-12f);
        float v  = g_gram[bh * (CPH * CPH) + c * CPH + d] / (nq * nk) * tv;
        vals[d] = v;
        mx = fmaxf(mx, v);
    }
    float sum = 0.f;
    #pragma unroll 4
    for (int d = 0; d < CPH; d++) {
        vals[d] = expf(vals[d] - mx);
        sum += vals[d];
    }
    const float inv = 1.f / sum;
    #pragma unroll 4
    for (int d = 0; d < CPH; d++)
        g_attn[bh * (CPH * CPH) + c * CPH + d] = vals[d] * inv;
}

// ---------------- M = proj @ blockdiag(attn) ----------------
__global__ void k_mixW(const float* __restrict__ proj_w)
{
    const int o  = blockIdx.x;
    const int b  = blockIdx.y;
    const int dg = threadIdx.x;
    const int h  = dg / CPH;
    const int d  = dg % CPH;
    float s = 0.f;
    #pragma unroll 8
    for (int cl = 0; cl < CPH; cl++)
        s += proj_w[o * C + h * CPH + cl] *
             g_attn[((size_t)(b * NH + h)) * (CPH * CPH) + cl * CPH + d];
    g_M[((size_t)b * C + o) * C + dg] = s;
}

// ---------------- launch ----------------
extern "C" void kernel_launch(void* const* d_in, const int* in_sizes, int n_in,
                              void* d_out, int out_size)
{
    const float* x      = (const float*)d_in[0];
    const float* qkv_w  = (const float*)d_in[1];
    const float* dw_w   = (const float*)d_in[2];
    const float* proj_w = (const float*)d_in[3];
    const float* temp   = (const float*)d_in[4];
    float* out = (float*)d_out;

    float *p_qkv, *p_M;
    __nv_bfloat16 *p_xh, *p_xl, *p_wh, *p_wl, *p_dh, *p_dl, *p_Mh, *p_Ml;
    cudaGetSymbolAddress((void**)&p_qkv, g_qkv);
    cudaGetSymbolAddress((void**)&p_M,   g_M);
    cudaGetSymbolAddress((void**)&p_xh,  g_x_hi);
    cudaGetSymbolAddress((void**)&p_xl,  g_x_lo);
    cudaGetSymbolAddress((void**)&p_wh,  g_w_hi);
    cudaGetSymbolAddress((void**)&p_wl,  g_w_lo);
    cudaGetSymbolAddress((void**)&p_dh,  g_dw_hi);
    cudaGetSymbolAddress((void**)&p_dl,  g_dw_lo);
    cudaGetSymbolAddress((void**)&p_Mh,  g_M_hi);
    cudaGetSymbolAddress((void**)&p_Ml,  g_M_lo);

    cudaFuncSetAttribute(gemm_bf16_pipe, cudaFuncAttributeMaxDynamicSharedMemorySize, GSMEM_BYTES);

    // 0) split x and weights to bf16 hi/lo
    {
        int n4 = B * C * HW / 4;
        k_cvt<<<(n4 + 255) / 256, 256>>>(x, p_xh, p_xl, n4);
        int w4 = C3 * C / 4;
        k_cvt<<<(w4 + 255) / 256, 256>>>(qkv_w, p_wh, p_wl, w4);
    }

    // 1) qkv = W @ x  ([576x192]@[192x65536] per batch)
    gemm_bf16_pipe<<<dim3(HW / GBN, C3 / GBM, B), 256, GSMEM_BYTES>>>(
        p_wh, p_wl, 0, p_xh, p_xl, (size_t)C * HW, p_qkv, (size_t)C3 * HW);

    // 2) depthwise conv + sumsq
    k_dwconv<<<dim3(IMG / DW_ROWS, C3, B), 256>>>(dw_w);
    k_ssq_reduce<<<(B * 2 * C + 255) / 256, 256>>>();

    // 3) Gram + reduce
    k_gram<<<dim3(64, NH, B), 256>>>();
    k_gram_reduce<<<(B * NH * CPH * CPH + 255) / 256, 256>>>();

    // 4) softmax, fold proj, split M
    k_softmax<<<B * NH, 64>>>(temp);
    k_mixW<<<dim3(C, B), C>>>(proj_w);
    {
        int m4 = B * C * C / 4;
        k_cvt<<<(m4 + 255) / 256, 256>>>(p_M, p_Mh, p_Ml, m4);
    }

    // 5) out = M @ v  ([192x192]@[192x65536] per batch)
    gemm_bf16_pipe<<<dim3(HW / GBN, C / GBM, B), 256, GSMEM_BYTES>>>(
        p_Mh, p_Ml, (size_t)C * C,
        p_dh + (size_t)2 * C * HW, p_dl + (size_t)2 * C * HW, (size_t)C3 * HW,
        out, (size_t)C * HW);
}

// round 6
// speedup vs baseline: 3.3322x; 1.1014x over previous
#include <cuda_runtime.h>
#include <cuda_bf16.h>
#include <math.h>
#include <stdint.h>

// Problem constants
#define B 4
#define C 192
#define C3 576
#define NH 4
#define CPH 48
#define HW 65536
#define IMG 256
#define DW_ROWS 32

// ---------------- device scratch ----------------
__device__ float g_qkv[(size_t)B * C3 * HW];
__device__ __nv_bfloat16 g_dw_hi[(size_t)B * C3 * HW];
__device__ __nv_bfloat16 g_dw_lo[(size_t)B * C3 * HW];
__device__ __nv_bfloat16 g_x_hi[(size_t)B * C * HW];
__device__ __nv_bfloat16 g_x_lo[(size_t)B * C * HW];
__device__ __nv_bfloat16 g_w_hi[C3 * C];
__device__ __nv_bfloat16 g_w_lo[C3 * C];
__device__ __nv_bfloat16 g_M_hi[B * C * C];
__device__ __nv_bfloat16 g_M_lo[B * C * C];
__device__ float g_ssq_part[B * 2 * C * (IMG / DW_ROWS)];
__device__ float g_sumsq[2][B * C];
__device__ float g_gram_part[(size_t)B * NH * 64 * CPH * CPH];
__device__ float g_gram[B * NH * CPH * CPH];
__device__ float g_attn[B * NH * CPH * CPH];
__device__ float g_M[B * C * C];

union BF4 { __nv_bfloat16 h[4]; uint2 u; };

// ---------------- fp32 -> bf16 hi/lo split ----------------
__global__ void k_cvt(const float* __restrict__ src,
                      __nv_bfloat16* __restrict__ hi,
                      __nv_bfloat16* __restrict__ lo, int n4)
{
    int i = blockIdx.x * 256 + threadIdx.x;
    if (i >= n4) return;
    float4 v = ((const float4*)src)[i];
    BF4 hh, ll;
    float vv[4] = {v.x, v.y, v.z, v.w};
    #pragma unroll
    for (int j = 0; j < 4; j++) {
        hh.h[j] = __float2bfloat16_rn(vv[j]);
        ll.h[j] = __float2bfloat16_rn(vv[j] - __bfloat162float(hh.h[j]));
    }
    ((uint2*)hi)[i] = hh.u;
    ((uint2*)lo)[i] = ll.u;
}

// ---------------- HMMA helpers ----------------
__device__ __forceinline__ void ldsm_x4(uint32_t& r0, uint32_t& r1, uint32_t& r2, uint32_t& r3, uint32_t addr) {
    asm volatile("ldmatrix.sync.aligned.m8n8.x4.shared.b16 {%0,%1,%2,%3}, [%4];"
                 : "=r"(r0), "=r"(r1), "=r"(r2), "=r"(r3) : "r"(addr));
}
__device__ __forceinline__ void ldsm_x2t(uint32_t& r0, uint32_t& r1, uint32_t addr) {
    asm volatile("ldmatrix.sync.aligned.m8n8.x2.trans.shared.b16 {%0,%1}, [%2];"
                 : "=r"(r0), "=r"(r1) : "r"(addr));
}
__device__ __forceinline__ void mma16816(float* d, const uint32_t* a, const uint32_t* b) {
    asm volatile("mma.sync.aligned.m16n8k16.row.col.f32.bf16.bf16.f32 "
                 "{%0,%1,%2,%3}, {%4,%5,%6,%7}, {%8,%9}, {%0,%1,%2,%3};"
                 : "+f"(d[0]), "+f"(d[1]), "+f"(d[2]), "+f"(d[3])
                 : "r"(a[0]), "r"(a[1]), "r"(a[2]), "r"(a[3]), "r"(b[0]), "r"(b[1]));
}
__device__ __forceinline__ void cp16(uint32_t saddr, const void* gptr) {
    asm volatile("cp.async.cg.shared.global [%0], [%1], 16;" :: "r"(saddr), "l"(gptr));
}
__device__ __forceinline__ uint32_t cvta_s(const void* p) {
    return (uint32_t)__cvta_generic_to_shared(p);
}

// Pipelined bf16-split GEMM, tall tiles for operand reuse.
// C[b][m][n] = sum_k (Ahi+Alo)[m][k]*(Xhi+Xlo)[k][n], K=192, N=HW.
// BM=192, BN=128, BK=32, 256 threads = 8 warps (4m x 2n), warp tile 48x64.
#define GBM 192
#define GBN 128
#define GBK 32
#define AS_STRIDE 40
#define BS_STRIDE 136
#define AS_Z   (GBM * AS_STRIDE)                 // 7680
#define AS_ST  (2 * AS_Z)                        // 15360
#define BS_Z   (GBK * BS_STRIDE)                 // 4352
#define BS_ST  (2 * BS_Z)                        // 8704
#define BS_BASE (2 * AS_ST)                      // 30720 elements
#define GSMEM_BYTES ((BS_BASE + 2 * BS_ST) * 2)  // 96256 bytes

__global__ __launch_bounds__(256) void gemm_bf16_pipe(
    const __nv_bfloat16* __restrict__ Ahi, const __nv_bfloat16* __restrict__ Alo, size_t aBatch,
    const __nv_bfloat16* __restrict__ Xhi, const __nv_bfloat16* __restrict__ Xlo, size_t xBatch,
    float* __restrict__ Cc, size_t cBatch)
{
    extern __shared__ __nv_bfloat16 smem[];
    const int b = blockIdx.z;
    Ahi += (size_t)b * aBatch;  Alo += (size_t)b * aBatch;
    Xhi += (size_t)b * xBatch;  Xlo += (size_t)b * xBatch;
    Cc  += (size_t)b * cBatch;

    const int n0 = blockIdx.x * GBN;
    const int m0 = blockIdx.y * GBM;

    const int t    = threadIdx.x;
    const int lane = t & 31;
    const int w    = t >> 5;
    const int wm   = w & 3;     // 0..3 -> m offset *48
    const int wn   = w >> 2;    // 0..1 -> n offset *64

    float acc[3][8][4];
    #pragma unroll
    for (int mi = 0; mi < 3; mi++)
        #pragma unroll
        for (int ni = 0; ni < 8; ni++)
            #pragma unroll
            for (int r = 0; r < 4; r++) acc[mi][ni][r] = 0.f;

    auto loadStage = [&](int st, int k0) {
        // A: 192 rows x 32 k, hi and lo : 3 cp16 per thread per z
        #pragma unroll
        for (int i = 0; i < 3; i++) {
            int e   = t + i * 256;
            int row = e >> 2;
            int kq  = (e & 3) * 8;
            const size_t gsrc = (size_t)(m0 + row) * 192 + k0 + kq;
            cp16(cvta_s(&smem[st * AS_ST + 0 * AS_Z + row * AS_STRIDE + kq]), &Ahi[gsrc]);
            cp16(cvta_s(&smem[st * AS_ST + 1 * AS_Z + row * AS_STRIDE + kq]), &Alo[gsrc]);
        }
        // B: 32 k x 128 n, hi and lo : 2 cp16 per thread per z
        #pragma unroll
        for (int i = 0; i < 2; i++) {
            int e  = t + i * 256;
            int kr = e >> 4;
            int nc = (e & 15) * 8;
            const size_t gsrc = (size_t)(k0 + kr) * HW + n0 + nc;
            cp16(cvta_s(&smem[BS_BASE + st * BS_ST + 0 * BS_Z + kr * BS_STRIDE + nc]), &Xhi[gsrc]);
            cp16(cvta_s(&smem[BS_BASE + st * BS_ST + 1 * BS_Z + kr * BS_STRIDE + nc]), &Xlo[gsrc]);
        }
    };

    loadStage(0, 0);
    asm volatile("cp.async.commit_group;");

    #pragma unroll
    for (int it = 0; it < 6; it++) {
        const int st = it & 1;
        if (it < 5) {
            loadStage(st ^ 1, (it + 1) * GBK);
            asm volatile("cp.async.commit_group;");
            asm volatile("cp.async.wait_group 1;");
        } else {
            asm volatile("cp.async.wait_group 0;");
        }
        __syncthreads();

        const __nv_bfloat16* As = &smem[st * AS_ST];
        const __nv_bfloat16* Bs = &smem[BS_BASE + st * BS_ST];

        #pragma unroll
        for (int ks = 0; ks < GBK; ks += 16) {
            uint32_t afrag[2][3][4];   // [z][mi]
            uint32_t bfrag[2][8][2];   // [z][ni]
            #pragma unroll
            for (int z = 0; z < 2; z++) {
                #pragma unroll
                for (int mi = 0; mi < 3; mi++) {
                    int row = wm * 48 + mi * 16 + (lane & 15);
                    int col = ks + (lane >> 4) * 8;
                    ldsm_x4(afrag[z][mi][0], afrag[z][mi][1], afrag[z][mi][2], afrag[z][mi][3],
                            cvta_s(&As[z * AS_Z + row * AS_STRIDE + col]));
                }
                #pragma unroll
                for (int ni = 0; ni < 8; ni++) {
                    int kr = ks + (lane & 15);
                    int nc = wn * 64 + ni * 8;
                    ldsm_x2t(bfrag[z][ni][0], bfrag[z][ni][1],
                             cvta_s(&Bs[z * BS_Z + kr * BS_STRIDE + nc]));
                }
            }
            #pragma unroll
            for (int mi = 0; mi < 3; mi++)
                #pragma unroll
                for (int ni = 0; ni < 8; ni++) {
                    mma16816(acc[mi][ni], afrag[0][mi], bfrag[0][ni]);  // hi*hi
                    mma16816(acc[mi][ni], afrag[0][mi], bfrag[1][ni]);  // hi*lo
                    mma16816(acc[mi][ni], afrag[1][mi], bfrag[0][ni]);  // lo*hi
                }
        }
        __syncthreads();
    }

    #pragma unroll
    for (int mi = 0; mi < 3; mi++)
        #pragma unroll
        for (int ni = 0; ni < 8; ni++) {
            int row = m0 + wm * 48 + mi * 16 + (lane >> 2);
            int col = n0 + wn * 64 + ni * 8 + 2 * (lane & 3);
            *(float2*)&Cc[(size_t)row * HW + col]       = *(float2*)&acc[mi][ni][0];
            *(float2*)&Cc[(size_t)(row + 8) * HW + col] = *(float2*)&acc[mi][ni][2];
        }
}

// ---------------- tiled depthwise 3x3 conv + fused sumsq (4 cols/thread) -------
// Block: (b, ch, 32-row band). 256 threads = 64 col-groups x 4 row-groups.
__global__ __launch_bounds__(256) void k_dwconv(const float* __restrict__ w)
{
    const int ch = blockIdx.y;
    const int b  = blockIdx.z;
    const int y0 = blockIdx.x * DW_ROWS;
    const int t  = threadIdx.x;
    const int tx = t & 63;     // column group (4 cols each)
    const int ty = t >> 6;     // row group (8 rows each)

    __shared__ float tile[DW_ROWS + 2][264];   // data cols 4..259, halo zeros at 3 and 260

    const float w0 = __ldg(&w[ch * 9 + 0]), w1 = __ldg(&w[ch * 9 + 1]), w2 = __ldg(&w[ch * 9 + 2]);
    const float w3 = __ldg(&w[ch * 9 + 3]), w4 = __ldg(&w[ch * 9 + 4]), w5 = __ldg(&w[ch * 9 + 5]);
    const float w6 = __ldg(&w[ch * 9 + 6]), w7 = __ldg(&w[ch * 9 + 7]), w8 = __ldg(&w[ch * 9 + 8]);

    const float* src = g_qkv + ((size_t)b * C3 + ch) * HW;

    // fill tile: 34 rows x 64 float4
    for (int i = t; i < (DW_ROWS + 2) * 64; i += 256) {
        int r = i >> 6;
        int j = i & 63;
        int y = y0 + r - 1;
        float4 v = make_float4(0.f, 0.f, 0.f, 0.f);
        if (y >= 0 && y < IMG) v = *(const float4*)&src[y * IMG + j * 4];
        *(float4*)&tile[r][4 + 4 * j] = v;
    }
    if (t < DW_ROWS + 2) { tile[t][3] = 0.f; tile[t][260] = 0.f; }
    __syncthreads();

    __nv_bfloat16* hi = g_dw_hi + ((size_t)b * C3 + ch) * HW;
    __nv_bfloat16* lo = g_dw_lo + ((size_t)b * C3 + ch) * HW;

    // sliding 3-row window of 6 columns
    float r0[6], r1[6], r2[6];
    const int cb = 4 * tx;
    #define LOADROW(dst, R) do {                               \
        float4 mq = *(const float4*)&tile[(R)][4 + cb];        \
        dst[0] = tile[(R)][3 + cb];                            \
        dst[1] = mq.x; dst[2] = mq.y; dst[3] = mq.z; dst[4] = mq.w; \
        dst[5] = tile[(R)][8 + cb];                            \
    } while (0)

    LOADROW(r0, ty * 8 + 0);
    LOADROW(r1, ty * 8 + 1);

    float ssq = 0.f;
    #pragma unroll
    for (int r = 0; r < 8; r++) {
        LOADROW(r2, ty * 8 + r + 2);
        float s[4];
        BF4 hh, ll;
        #pragma unroll
        for (int c = 0; c < 4; c++) {
            s[c] = w0 * r0[c] + w1 * r0[c + 1] + w2 * r0[c + 2]
                 + w3 * r1[c] + w4 * r1[c + 1] + w5 * r1[c + 2]
                 + w6 * r2[c] + w7 * r2[c + 1] + w8 * r2[c + 2];
            hh.h[c] = __float2bfloat16_rn(s[c]);
            ll.h[c] = __float2bfloat16_rn(s[c] - __bfloat162float(hh.h[c]));
            ssq += s[c] * s[c];
        }
        const int p = (y0 + ty * 8 + r) * IMG + cb;
        *(uint2*)&hi[p] = hh.u;
        *(uint2*)&lo[p] = ll.u;
        #pragma unroll
        for (int c = 0; c < 6; c++) { r0[c] = r1[c]; r1[c] = r2[c]; }
    }
    #undef LOADROW

    if (ch < 2 * C) {
        #pragma unroll
        for (int st = 16; st > 0; st >>= 1)
            ssq += __shfl_xor_sync(0xffffffffu, ssq, st);
        __shared__ float wred[8];
        if ((t & 31) == 0) wred[t >> 5] = ssq;
        __syncthreads();
        if (t == 0) {
            float s = 0.f;
            #pragma unroll
            for (int i = 0; i < 8; i++) s += wred[i];
            g_ssq_part[((size_t)b * 2 * C + ch) * (IMG / DW_ROWS) + blockIdx.x] = s;
        }
    }
}

__global__ void k_ssq_reduce()
{
    const int idx = blockIdx.x * blockDim.x + threadIdx.x;
    if (idx >= B * 2 * C) return;
    float s = 0.f;
    #pragma unroll
    for (int i = 0; i < IMG / DW_ROWS; i++)
        s += g_ssq_part[(size_t)idx * (IMG / DW_ROWS) + i];
    const int b  = idx / (2 * C);
    const int ch = idx % (2 * C);
    g_sumsq[ch / C][b * C + ch % C] = s;
}

// ---------------- Gram partials ----------------
__global__ __launch_bounds__(256) void k_gram()
{
    const int chunk = blockIdx.x;
    const int h     = blockIdx.y;
    const int b     = blockIdx.z;

    __shared__ float Qs[64][49];
    __shared__ float Ks[64][49];

    const size_t qoff = ((size_t)b * C3 + h * CPH) * HW + (size_t)chunk * 1024;
    const __nv_bfloat16* qh = g_dw_hi + qoff;
    const __nv_bfloat16* ql = g_dw_lo + qoff;
    const __nv_bfloat16* kh = qh + (size_t)C * HW;
    const __nv_bfloat16* kl = ql + (size_t)C * HW;

    const int t  = threadIdx.x;
    const int tx = t & 15;
    const int ty = t >> 4;

    float acc[3][3];
    #pragma unroll
    for (int i = 0; i < 3; i++)
        #pragma unroll
        for (int j = 0; j < 3; j++) acc[i][j] = 0.f;

    for (int nt = 0; nt < 1024; nt += 64) {
        #pragma unroll
        for (int i = 0; i < 3; i++) {
            int e   = t + i * 256;
            int row = e >> 4;
            int c4  = (e & 15) * 4;
            size_t o = (size_t)row * HW + nt + c4;
            BF4 vh, vl;
            vh.u = *(const uint2*)&qh[o];
            vl.u = *(const uint2*)&ql[o];
            #pragma unroll
            for (int j = 0; j < 4; j++)
                Qs[c4 + j][row] = __bfloat162float(vh.h[j]) + __bfloat162float(vl.h[j]);
            vh.u = *(const uint2*)&kh[o];
            vl.u = *(const uint2*)&kl[o];
            #pragma unroll
            for (int j = 0; j < 4; j++)
                Ks[c4 + j][row] = __bfloat162float(vh.h[j]) + __bfloat162float(vl.h[j]);
        }
        __syncthreads();
        #pragma unroll 8
        for (int kk = 0; kk < 64; kk++) {
            float a[3], bb[3];
            #pragma unroll
            for (int i = 0; i < 3; i++) a[i]  = Qs[kk][ty * 3 + i];
            #pragma unroll
            for (int j = 0; j < 3; j++) bb[j] = Ks[kk][tx * 3 + j];
            #pragma unroll
            for (int i = 0; i < 3; i++)
                #pragma unroll
                for (int j = 0; j < 3; j++)
                    acc[i][j] += a[i] * bb[j];
        }
        __syncthreads();
    }

    const size_t base = (((size_t)(b * NH + h)) * 64 + chunk) * (CPH * CPH);
    #pragma unroll
    for (int i = 0; i < 3; i++)
        #pragma unroll
        for (int j = 0; j < 3; j++)
            g_gram_part[base + (ty * 3 + i) * CPH + tx * 3 + j] = acc[i][j];
}

__global__ void k_gram_reduce()
{
    const int idx = blockIdx.x * blockDim.x + threadIdx.x;
    if (idx >= B * NH * CPH * CPH) return;
    const int bh = idx / (CPH * CPH);
    const int cd = idx % (CPH * CPH);
    float s = 0.f;
    for (int ck = 0; ck < 64; ck++)
        s += g_gram_part[((size_t)bh * 64 + ck) * (CPH * CPH) + cd];
    g_gram[idx] = s;
}

// ---------------- softmax ----------------
__global__ void k_softmax(const float* __restrict__ temperature)
{
    const int bh = blockIdx.x;
    const int b  = bh >> 2;
    const int h  = bh & 3;
    const int c  = threadIdx.x;
    if (c >= CPH) return;

    const float tv = temperature[h];
    const float nq = fmaxf(sqrtf(g_sumsq[0][b * C + h * CPH + c]), 1e-12f);

    float vals[CPH];
    float mx = -1e30f;
    #pragma unroll 4
    for (int d = 0; d < CPH; d++) {
        float nk = fmaxf(sqrtf(g_sumsq[1][b * C + h * CPH + d]), 1e-12f);
        float v  = g_gram[bh * (CPH * CPH) + c * CPH + d] / (nq * nk) * tv;
        vals[d] = v;
        mx = fmaxf(mx, v);
    }
    float sum = 0.f;
    #pragma unroll 4
    for (int d = 0; d < CPH; d++) {
        vals[d] = expf(vals[d] - mx);
        sum += vals[d];
    }
    const float inv = 1.f / sum;
    #pragma unroll 4
    for (int d = 0; d < CPH; d++)
        g_attn[bh * (CPH * CPH) + c * CPH + d] = vals[d] * inv;
}

// ---------------- M = proj @ blockdiag(attn) ----------------
__global__ void k_mixW(const float* __restrict__ proj_w)
{
    const int o  = blockIdx.x;
    const int b  = blockIdx.y;
    const int dg = threadIdx.x;
    const int h  = dg / CPH;
    const int d  = dg % CPH;
    float s = 0.f;
    #pragma unroll 8
    for (int cl = 0; cl < CPH; cl++)
        s += proj_w[o * C + h * CPH + cl] *
             g_attn[((size_t)(b * NH + h)) * (CPH * CPH) + cl * CPH + d];
    g_M[((size_t)b * C + o) * C + dg] = s;
}

// ---------------- launch ----------------
extern "C" void kernel_launch(void* const* d_in, const int* in_sizes, int n_in,
                              void* d_out, int out_size)
{
    const float* x      = (const float*)d_in[0];
    const float* qkv_w  = (const float*)d_in[1];
    const float* dw_w   = (const float*)d_in[2];
    const float* proj_w = (const float*)d_in[3];
    const float* temp   = (const float*)d_in[4];
    float* out = (float*)d_out;

    float *p_qkv, *p_M;
    __nv_bfloat16 *p_xh, *p_xl, *p_wh, *p_wl, *p_dh, *p_dl, *p_Mh, *p_Ml;
    cudaGetSymbolAddress((void**)&p_qkv, g_qkv);
    cudaGetSymbolAddress((void**)&p_M,   g_M);
    cudaGetSymbolAddress((void**)&p_xh,  g_x_hi);
    cudaGetSymbolAddress((void**)&p_xl,  g_x_lo);
    cudaGetSymbolAddress((void**)&p_wh,  g_w_hi);
    cudaGetSymbolAddress((void**)&p_wl,  g_w_lo);
    cudaGetSymbolAddress((void**)&p_dh,  g_dw_hi);
    cudaGetSymbolAddress((void**)&p_dl,  g_dw_lo);
    cudaGetSymbolAddress((void**)&p_Mh,  g_M_hi);
    cudaGetSymbolAddress((void**)&p_Ml,  g_M_lo);

    cudaFuncSetAttribute(gemm_bf16_pipe, cudaFuncAttributeMaxDynamicSharedMemorySize, GSMEM_BYTES);

    // 0) split x and weights to bf16 hi/lo
    {
        int n4 = B * C * HW / 4;
        k_cvt<<<(n4 + 255) / 256, 256>>>(x, p_xh, p_xl, n4);
        int w4 = C3 * C / 4;
        k_cvt<<<(w4 + 255) / 256, 256>>>(qkv_w, p_wh, p_wl, w4);
    }

    // 1) qkv = W @ x  ([576x192]@[192x65536] per batch, 3 m-tiles)
    gemm_bf16_pipe<<<dim3(HW / GBN, C3 / GBM, B), 256, GSMEM_BYTES>>>(
        p_wh, p_wl, 0, p_xh, p_xl, (size_t)C * HW, p_qkv, (size_t)C3 * HW);

    // 2) depthwise conv + sumsq
    k_dwconv<<<dim3(IMG / DW_ROWS, C3, B), 256>>>(dw_w);
    k_ssq_reduce<<<(B * 2 * C + 255) / 256, 256>>>();

    // 3) Gram + reduce
    k_gram<<<dim3(64, NH, B), 256>>>();
    k_gram_reduce<<<(B * NH * CPH * CPH + 255) / 256, 256>>>();

    // 4) softmax, fold proj, split M
    k_softmax<<<B * NH, 64>>>(temp);
    k_mixW<<<dim3(C, B), C>>>(proj_w);
    {
        int m4 = B * C * C / 4;
        k_cvt<<<(m4 + 255) / 256, 256>>>(p_M, p_Mh, p_Ml, m4);
    }

    // 5) out = M @ v  ([192x192]@[192x65536] per batch, single m-tile)
    gemm_bf16_pipe<<<dim3(HW / GBN, C / GBM, B), 256, GSMEM_BYTES>>>(
        p_Mh, p_Ml, (size_t)C * C,
        p_dh + (size_t)2 * C * HW, p_dl + (size_t)2 * C * HW, (size_t)C3 * HW,
        out, (size_t)C * HW);
}

// round 7
// speedup vs baseline: 3.5063x; 1.0523x over previous
#include <cuda_runtime.h>
#include <cuda_bf16.h>
#include <math.h>
#include <stdint.h>

// Problem constants
#define B 4
#define C 192
#define C3 576
#define NH 4
#define CPH 48
#define HW 65536
#define IMG 256
#define DW_ROWS 32

// ---------------- device scratch ----------------
__device__ float g_qkv[(size_t)B * C3 * HW];
__device__ __nv_bfloat16 g_dw_hi[(size_t)B * C3 * HW];
__device__ __nv_bfloat16 g_dw_lo[(size_t)B * C3 * HW];
__device__ __nv_bfloat16 g_w_hi[C3 * C];
__device__ __nv_bfloat16 g_w_lo[C3 * C];
__device__ __nv_bfloat16 g_M_hi[B * C * C];
__device__ __nv_bfloat16 g_M_lo[B * C * C];
__device__ float g_ssq_part[B * 2 * C * (IMG / DW_ROWS)];
__device__ float g_sumsq[2][B * C];
__device__ float g_gram_part[(size_t)B * NH * 64 * CPH * CPH];
__device__ float g_gram[B * NH * CPH * CPH];
__device__ float g_attn[B * NH * CPH * CPH];
__device__ float g_M[B * C * C];

union BF4 { __nv_bfloat16 h[4]; uint2 u; };

// ---------------- fp32 -> bf16 hi/lo split (small tensors only) ----------------
__global__ void k_cvt(const float* __restrict__ src,
                      __nv_bfloat16* __restrict__ hi,
                      __nv_bfloat16* __restrict__ lo, int n4)
{
    int i = blockIdx.x * 256 + threadIdx.x;
    if (i >= n4) return;
    float4 v = ((const float4*)src)[i];
    BF4 hh, ll;
    float vv[4] = {v.x, v.y, v.z, v.w};
    #pragma unroll
    for (int j = 0; j < 4; j++) {
        hh.h[j] = __float2bfloat16_rn(vv[j]);
        ll.h[j] = __float2bfloat16_rn(vv[j] - __bfloat162float(hh.h[j]));
    }
    ((uint2*)hi)[i] = hh.u;
    ((uint2*)lo)[i] = ll.u;
}

// ---------------- HMMA helpers ----------------
__device__ __forceinline__ void ldsm_x4(uint32_t& r0, uint32_t& r1, uint32_t& r2, uint32_t& r3, uint32_t addr) {
    asm volatile("ldmatrix.sync.aligned.m8n8.x4.shared.b16 {%0,%1,%2,%3}, [%4];"
                 : "=r"(r0), "=r"(r1), "=r"(r2), "=r"(r3) : "r"(addr));
}
__device__ __forceinline__ void ldsm_x4t(uint32_t& r0, uint32_t& r1, uint32_t& r2, uint32_t& r3, uint32_t addr) {
    asm volatile("ldmatrix.sync.aligned.m8n8.x4.trans.shared.b16 {%0,%1,%2,%3}, [%4];"
                 : "=r"(r0), "=r"(r1), "=r"(r2), "=r"(r3) : "r"(addr));
}
__device__ __forceinline__ void mma16816(float* d, const uint32_t* a, const uint32_t* b) {
    asm volatile("mma.sync.aligned.m16n8k16.row.col.f32.bf16.bf16.f32 "
                 "{%0,%1,%2,%3}, {%4,%5,%6,%7}, {%8,%9}, {%0,%1,%2,%3};"
                 : "+f"(d[0]), "+f"(d[1]), "+f"(d[2]), "+f"(d[3])
                 : "r"(a[0]), "r"(a[1]), "r"(a[2]), "r"(a[3]), "r"(b[0]), "r"(b[1]));
}
__device__ __forceinline__ void cp16(uint32_t saddr, const void* gptr) {
    asm volatile("cp.async.cg.shared.global [%0], [%1], 16;" :: "r"(saddr), "l"(gptr));
}
__device__ __forceinline__ uint32_t cvta_s(const void* p) {
    return (uint32_t)__cvta_generic_to_shared(p);
}

#define GBM 192
#define GBN 128
#define GBK 32
#define AS_STRIDE 40
#define BS_STRIDE 136

// ===================== GEMM1: fused x conversion =====================
// A = weights bf16 hi/lo [576x192] (shared over batches), X = fp32 [192xHW].
// smem: As 2stages x 2z x 192x40 bf16 (61440B), Bs 2z x 32x136 bf16 (17408B),
//       Bf32 2stages x 32x132 fp32 (33792B). total 112640B.
#define G1_AS_STG 15360   // elems per stage (2z)
#define G1_AS_Z   7680
#define G1_BS_OFF 61440   // bytes
#define G1_BS_Z   4352    // elems
#define G1_BF_OFF 78848   // bytes
#define G1_BF_STG 4224    // floats per stage
#define G1_SMEM   112640

__global__ __launch_bounds__(256) void gemm1_fused(
    const __nv_bfloat16* __restrict__ Ahi, const __nv_bfloat16* __restrict__ Alo,
    const float* __restrict__ X, float* __restrict__ Cc)
{
    extern __shared__ char smraw[];
    __nv_bfloat16* As = (__nv_bfloat16*)smraw;
    __nv_bfloat16* Bs = (__nv_bfloat16*)(smraw + G1_BS_OFF);
    float*         Bf = (float*)(smraw + G1_BF_OFF);

    const int b = blockIdx.z;
    X  += (size_t)b * C * HW;
    Cc += (size_t)b * C3 * HW;

    const int n0 = blockIdx.x * GBN;
    const int m0 = blockIdx.y * GBM;

    const int t    = threadIdx.x;
    const int lane = t & 31;
    const int w    = t >> 5;
    const int wm   = w & 3;
    const int wn   = w >> 2;

    float acc[3][8][4];
    #pragma unroll
    for (int mi = 0; mi < 3; mi++)
        #pragma unroll
        for (int ni = 0; ni < 8; ni++)
            #pragma unroll
            for (int r = 0; r < 4; r++) acc[mi][ni][r] = 0.f;

    auto loadStage = [&](int st, int k0) {
        #pragma unroll
        for (int i = 0; i < 3; i++) {
            int e   = t + i * 256;
            int row = e >> 2;
            int kq  = (e & 3) * 8;
            const size_t gsrc = (size_t)(m0 + row) * 192 + k0 + kq;
            cp16(cvta_s(&As[st * G1_AS_STG + 0 * G1_AS_Z + row * AS_STRIDE + kq]), &Ahi[gsrc]);
            cp16(cvta_s(&As[st * G1_AS_STG + 1 * G1_AS_Z + row * AS_STRIDE + kq]), &Alo[gsrc]);
        }
        #pragma unroll
        for (int i = 0; i < 4; i++) {
            int e   = t + i * 256;
            int kr  = e >> 5;
            int nc4 = (e & 31) * 4;
            cp16(cvta_s(&Bf[st * G1_BF_STG + kr * 132 + nc4]),
                 &X[(size_t)(k0 + kr) * HW + n0 + nc4]);
        }
    };

    loadStage(0, 0);
    asm volatile("cp.async.commit_group;");

    #pragma unroll
    for (int it = 0; it < 6; it++) {
        const int st = it & 1;
        if (it < 5) {
            loadStage(st ^ 1, (it + 1) * GBK);
            asm volatile("cp.async.commit_group;");
            asm volatile("cp.async.wait_group 1;");
        } else {
            asm volatile("cp.async.wait_group 0;");
        }
        __syncthreads();

        // convert fp32 stage -> hi/lo bf16 Bs (single buffer)
        #pragma unroll
        for (int i = 0; i < 4; i++) {
            int e   = t + i * 256;
            int kr  = e >> 5;
            int nc4 = (e & 31) * 4;
            float4 v = *(float4*)&Bf[st * G1_BF_STG + kr * 132 + nc4];
            BF4 hh, ll;
            float vv[4] = {v.x, v.y, v.z, v.w};
            #pragma unroll
            for (int j = 0; j < 4; j++) {
                hh.h[j] = __float2bfloat16_rn(vv[j]);
                ll.h[j] = __float2bfloat16_rn(vv[j] - __bfloat162float(hh.h[j]));
            }
            *(uint2*)&Bs[0 * G1_BS_Z + kr * BS_STRIDE + nc4] = hh.u;
            *(uint2*)&Bs[1 * G1_BS_Z + kr * BS_STRIDE + nc4] = ll.u;
        }
        __syncthreads();

        const __nv_bfloat16* Asl = &As[st * G1_AS_STG];

        #pragma unroll
        for (int ks = 0; ks < GBK; ks += 16) {
            uint32_t afrag[2][3][4];
            uint32_t bfrag[2][8][2];
            #pragma unroll
            for (int z = 0; z < 2; z++) {
                #pragma unroll
                for (int mi = 0; mi < 3; mi++) {
                    int row = wm * 48 + mi * 16 + (lane & 15);
                    int col = ks + (lane >> 4) * 8;
                    ldsm_x4(afrag[z][mi][0], afrag[z][mi][1], afrag[z][mi][2], afrag[z][mi][3],
                            cvta_s(&Asl[z * G1_AS_Z + row * AS_STRIDE + col]));
                }
                #pragma unroll
                for (int np = 0; np < 4; np++) {
                    int kr = ks + (lane & 15);
                    int nc = wn * 64 + np * 16 + (lane >> 4) * 8;
                    ldsm_x4t(bfrag[z][2*np][0], bfrag[z][2*np][1],
                             bfrag[z][2*np+1][0], bfrag[z][2*np+1][1],
                             cvta_s(&Bs[z * G1_BS_Z + kr * BS_STRIDE + nc]));
                }
            }
            #pragma unroll
            for (int mi = 0; mi < 3; mi++)
                #pragma unroll
                for (int ni = 0; ni < 8; ni++) {
                    mma16816(acc[mi][ni], afrag[0][mi], bfrag[0][ni]);
                    mma16816(acc[mi][ni], afrag[0][mi], bfrag[1][ni]);
                    mma16816(acc[mi][ni], afrag[1][mi], bfrag[0][ni]);
                }
        }
        __syncthreads();
    }

    #pragma unroll
    for (int mi = 0; mi < 3; mi++)
        #pragma unroll
        for (int ni = 0; ni < 8; ni++) {
            int row = m0 + wm * 48 + mi * 16 + (lane >> 2);
            int col = n0 + wn * 64 + ni * 8 + 2 * (lane & 3);
            *(float2*)&Cc[(size_t)row * HW + col]       = *(float2*)&acc[mi][ni][0];
            *(float2*)&Cc[(size_t)(row + 8) * HW + col] = *(float2*)&acc[mi][ni][2];
        }
}

// ===================== GEMM2: pure bf16 hi/lo (pipelined) =====================
#define AS_Z   (GBM * AS_STRIDE)
#define AS_ST  (2 * AS_Z)
#define BS_Z   (GBK * BS_STRIDE)
#define BS_ST  (2 * BS_Z)
#define BS_BASE (2 * AS_ST)
#define GSMEM_BYTES ((BS_BASE + 2 * BS_ST) * 2)

__global__ __launch_bounds__(256) void gemm_bf16_pipe(
    const __nv_bfloat16* __restrict__ Ahi, const __nv_bfloat16* __restrict__ Alo, size_t aBatch,
    const __nv_bfloat16* __restrict__ Xhi, const __nv_bfloat16* __restrict__ Xlo, size_t xBatch,
    float* __restrict__ Cc, size_t cBatch)
{
    extern __shared__ __nv_bfloat16 smem[];
    const int b = blockIdx.z;
    Ahi += (size_t)b * aBatch;  Alo += (size_t)b * aBatch;
    Xhi += (size_t)b * xBatch;  Xlo += (size_t)b * xBatch;
    Cc  += (size_t)b * cBatch;

    const int n0 = blockIdx.x * GBN;
    const int m0 = blockIdx.y * GBM;

    const int t    = threadIdx.x;
    const int lane = t & 31;
    const int w    = t >> 5;
    const int wm   = w & 3;
    const int wn   = w >> 2;

    float acc[3][8][4];
    #pragma unroll
    for (int mi = 0; mi < 3; mi++)
        #pragma unroll
        for (int ni = 0; ni < 8; ni++)
            #pragma unroll
            for (int r = 0; r < 4; r++) acc[mi][ni][r] = 0.f;

    auto loadStage = [&](int st, int k0) {
        #pragma unroll
        for (int i = 0; i < 3; i++) {
            int e   = t + i * 256;
            int row = e >> 2;
            int kq  = (e & 3) * 8;
            const size_t gsrc = (size_t)(m0 + row) * 192 + k0 + kq;
            cp16(cvta_s(&smem[st * AS_ST + 0 * AS_Z + row * AS_STRIDE + kq]), &Ahi[gsrc]);
            cp16(cvta_s(&smem[st * AS_ST + 1 * AS_Z + row * AS_STRIDE + kq]), &Alo[gsrc]);
        }
        #pragma unroll
        for (int i = 0; i < 2; i++) {
            int e  = t + i * 256;
            int kr = e >> 4;
            int nc = (e & 15) * 8;
            const size_t gsrc = (size_t)(k0 + kr) * HW + n0 + nc;
            cp16(cvta_s(&smem[BS_BASE + st * BS_ST + 0 * BS_Z + kr * BS_STRIDE + nc]), &Xhi[gsrc]);
            cp16(cvta_s(&smem[BS_BASE + st * BS_ST + 1 * BS_Z + kr * BS_STRIDE + nc]), &Xlo[gsrc]);
        }
    };

    loadStage(0, 0);
    asm volatile("cp.async.commit_group;");

    #pragma unroll
    for (int it = 0; it < 6; it++) {
        const int st = it & 1;
        if (it < 5) {
            loadStage(st ^ 1, (it + 1) * GBK);
            asm volatile("cp.async.commit_group;");
            asm volatile("cp.async.wait_group 1;");
        } else {
            asm volatile("cp.async.wait_group 0;");
        }
        __syncthreads();

        const __nv_bfloat16* As = &smem[st * AS_ST];
        const __nv_bfloat16* Bs = &smem[BS_BASE + st * BS_ST];

        #pragma unroll
        for (int ks = 0; ks < GBK; ks += 16) {
            uint32_t afrag[2][3][4];
            uint32_t bfrag[2][8][2];
            #pragma unroll
            for (int z = 0; z < 2; z++) {
                #pragma unroll
                for (int mi = 0; mi < 3; mi++) {
                    int row = wm * 48 + mi * 16 + (lane & 15);
                    int col = ks + (lane >> 4) * 8;
                    ldsm_x4(afrag[z][mi][0], afrag[z][mi][1], afrag[z][mi][2], afrag[z][mi][3],
                            cvta_s(&As[z * AS_Z + row * AS_STRIDE + col]));
                }
                #pragma unroll
                for (int np = 0; np < 4; np++) {
                    int kr = ks + (lane & 15);
                    int nc = wn * 64 + np * 16 + (lane >> 4) * 8;
                    ldsm_x4t(bfrag[z][2*np][0], bfrag[z][2*np][1],
                             bfrag[z][2*np+1][0], bfrag[z][2*np+1][1],
                             cvta_s(&Bs[z * BS_Z + kr * BS_STRIDE + nc]));
                }
            }
            #pragma unroll
            for (int mi = 0; mi < 3; mi++)
                #pragma unroll
                for (int ni = 0; ni < 8; ni++) {
                    mma16816(acc[mi][ni], afrag[0][mi], bfrag[0][ni]);
                    mma16816(acc[mi][ni], afrag[0][mi], bfrag[1][ni]);
                    mma16816(acc[mi][ni], afrag[1][mi], bfrag[0][ni]);
                }
        }
        __syncthreads();
    }

    #pragma unroll
    for (int mi = 0; mi < 3; mi++)
        #pragma unroll
        for (int ni = 0; ni < 8; ni++) {
            int row = m0 + wm * 48 + mi * 16 + (lane >> 2);
            int col = n0 + wn * 64 + ni * 8 + 2 * (lane & 3);
            *(float2*)&Cc[(size_t)row * HW + col]       = *(float2*)&acc[mi][ni][0];
            *(float2*)&Cc[(size_t)(row + 8) * HW + col] = *(float2*)&acc[mi][ni][2];
        }
}

// ---------------- tiled depthwise 3x3 conv + fused sumsq (4 cols/thread) -------
__global__ __launch_bounds__(256) void k_dwconv(const float* __restrict__ w)
{
    const int ch = blockIdx.y;
    const int b  = blockIdx.z;
    const int y0 = blockIdx.x * DW_ROWS;
    const int t  = threadIdx.x;
    const int tx = t & 63;
    const int ty = t >> 6;

    __shared__ float tile[DW_ROWS + 2][264];

    const float w0 = __ldg(&w[ch * 9 + 0]), w1 = __ldg(&w[ch * 9 + 1]), w2 = __ldg(&w[ch * 9 + 2]);
    const float w3 = __ldg(&w[ch * 9 + 3]), w4 = __ldg(&w[ch * 9 + 4]), w5 = __ldg(&w[ch * 9 + 5]);
    const float w6 = __ldg(&w[ch * 9 + 6]), w7 = __ldg(&w[ch * 9 + 7]), w8 = __ldg(&w[ch * 9 + 8]);

    const float* src = g_qkv + ((size_t)b * C3 + ch) * HW;

    for (int i = t; i < (DW_ROWS + 2) * 64; i += 256) {
        int r = i >> 6;
        int j = i & 63;
        int y = y0 + r - 1;
        float4 v = make_float4(0.f, 0.f, 0.f, 0.f);
        if (y >= 0 && y < IMG) v = *(const float4*)&src[y * IMG + j * 4];
        *(float4*)&tile[r][4 + 4 * j] = v;
    }
    if (t < DW_ROWS + 2) { tile[t][3] = 0.f; tile[t][260] = 0.f; }
    __syncthreads();

    __nv_bfloat16* hi = g_dw_hi + ((size_t)b * C3 + ch) * HW;
    __nv_bfloat16* lo = g_dw_lo + ((size_t)b * C3 + ch) * HW;

    float r0[6], r1[6], r2[6];
    const int cb = 4 * tx;
    #define LOADROW(dst, R) do {                               \
        float4 mq = *(const float4*)&tile[(R)][4 + cb];        \
        dst[0] = tile[(R)][3 + cb];                            \
        dst[1] = mq.x; dst[2] = mq.y; dst[3] = mq.z; dst[4] = mq.w; \
        dst[5] = tile[(R)][8 + cb];                            \
    } while (0)

    LOADROW(r0, ty * 8 + 0);
    LOADROW(r1, ty * 8 + 1);

    float ssq = 0.f;
    #pragma unroll
    for (int r = 0; r < 8; r++) {
        LOADROW(r2, ty * 8 + r + 2);
        float s[4];
        BF4 hh, ll;
        #pragma unroll
        for (int c = 0; c < 4; c++) {
            s[c] = w0 * r0[c] + w1 * r0[c + 1] + w2 * r0[c + 2]
                 + w3 * r1[c] + w4 * r1[c + 1] + w5 * r1[c + 2]
                 + w6 * r2[c] + w7 * r2[c + 1] + w8 * r2[c + 2];
            hh.h[c] = __float2bfloat16_rn(s[c]);
            ll.h[c] = __float2bfloat16_rn(s[c] - __bfloat162float(hh.h[c]));
            ssq += s[c] * s[c];
        }
        const int p = (y0 + ty * 8 + r) * IMG + cb;
        *(uint2*)&hi[p] = hh.u;
        *(uint2*)&lo[p] = ll.u;
        #pragma unroll
        for (int c = 0; c < 6; c++) { r0[c] = r1[c]; r1[c] = r2[c]; }
    }
    #undef LOADROW

    if (ch < 2 * C) {
        #pragma unroll
        for (int st = 16; st > 0; st >>= 1)
            ssq += __shfl_xor_sync(0xffffffffu, ssq, st);
        __shared__ float wred[8];
        if ((t & 31) == 0) wred[t >> 5] = ssq;
        __syncthreads();
        if (t == 0) {
            float s = 0.f;
            #pragma unroll
            for (int i = 0; i < 8; i++) s += wred[i];
            g_ssq_part[((size_t)b * 2 * C + ch) * (IMG / DW_ROWS) + blockIdx.x] = s;
        }
    }
}

__global__ void k_ssq_reduce()
{
    const int idx = blockIdx.x * blockDim.x + threadIdx.x;
    if (idx >= B * 2 * C) return;
    float s = 0.f;
    #pragma unroll
    for (int i = 0; i < IMG / DW_ROWS; i++)
        s += g_ssq_part[(size_t)idx * (IMG / DW_ROWS) + i];
    const int b  = idx / (2 * C);
    const int ch = idx % (2 * C);
    g_sumsq[ch / C][b * C + ch % C] = s;
}

// ---------------- Gram via HMMA: gram[c][d] = sum_n q[c,n]k[d,n] ----------------
// Block: 128 threads (4 warps; warps 0-2 compute m16 each). Grid: (32, NH, B).
__global__ __launch_bounds__(128) void k_gram_mma()
{
    const int chunk = blockIdx.x;   // 2048-pixel chunks
    const int h     = blockIdx.y;
    const int b     = blockIdx.z;

    __shared__ __nv_bfloat16 Qs[2][48][72];
    __shared__ __nv_bfloat16 Ks[2][64][56];

    const size_t qoff = ((size_t)b * C3 + h * CPH) * HW + (size_t)chunk * 2048;
    const __nv_bfloat16* qh = g_dw_hi + qoff;
    const __nv_bfloat16* ql = g_dw_lo + qoff;
    const __nv_bfloat16* kh = qh + (size_t)C * HW;
    const __nv_bfloat16* kl = ql + (size_t)C * HW;

    const int t    = threadIdx.x;
    const int lane = t & 31;
    const int w    = t >> 5;

    float acc[6][4];
    #pragma unroll
    for (int ni = 0; ni < 6; ni++)
        #pragma unroll
        for (int r = 0; r < 4; r++) acc[ni][r] = 0.f;

    for (int it = 0; it < 32; it++) {
        const int px0 = it * 64;
        #pragma unroll
        for (int i = 0; i < 6; i++) {
            int e   = t + i * 128;       // 0..767
            int row = e >> 4;            // ch 0..47
            int c4  = (e & 15) * 4;      // px 0..60
            size_t o = (size_t)row * HW + px0 + c4;
            *(uint2*)&Qs[0][row][c4] = *(const uint2*)&qh[o];
            *(uint2*)&Qs[1][row][c4] = *(const uint2*)&ql[o];
            BF4 vh, vl;
            vh.u = *(const uint2*)&kh[o];
            vl.u = *(const uint2*)&kl[o];
            #pragma unroll
            for (int j = 0; j < 4; j++) {
                Ks[0][c4 + j][row] = vh.h[j];
                Ks[1][c4 + j][row] = vl.h[j];
            }
        }
        __syncthreads();
        if (w < 3) {
            #pragma unroll
            for (int ks = 0; ks < 64; ks += 16) {
                uint32_t afrag[2][4], bfrag[2][6][2];
                #pragma unroll
                for (int z = 0; z < 2; z++) {
                    ldsm_x4(afrag[z][0], afrag[z][1], afrag[z][2], afrag[z][3],
                            cvta_s(&Qs[z][w * 16 + (lane & 15)][ks + (lane >> 4) * 8]));
                    #pragma unroll
                    for (int np = 0; np < 3; np++)
                        ldsm_x4t(bfrag[z][2*np][0], bfrag[z][2*np][1],
                                 bfrag[z][2*np+1][0], bfrag[z][2*np+1][1],
                                 cvta_s(&Ks[z][ks + (lane & 15)][np * 16 + (lane >> 4) * 8]));
                }
                #pragma unroll
                for (int ni = 0; ni < 6; ni++) {
                    mma16816(acc[ni], afrag[0], bfrag[0][ni]);
                    mma16816(acc[ni], afrag[0], bfrag[1][ni]);
                    mma16816(acc[ni], afrag[1], bfrag[0][ni]);
                }
            }
        }
        __syncthreads();
    }

    if (w < 3) {
        const size_t base = (((size_t)(b * NH + h)) * 32 + chunk) * (CPH * CPH);
        #pragma unroll
        for (int ni = 0; ni < 6; ni++) {
            int row = w * 16 + (lane >> 2);
            int col = ni * 8 + 2 * (lane & 3);
            *(float2*)&g_gram_part[base + (size_t)row * CPH + col]       = *(float2*)&acc[ni][0];
            *(float2*)&g_gram_part[base + (size_t)(row + 8) * CPH + col] = *(float2*)&acc[ni][2];
        }
    }
}

__global__ void k_gram_reduce()
{
    const int idx = blockIdx.x * blockDim.x + threadIdx.x;
    if (idx >= B * NH * CPH * CPH) return;
    const int bh = idx / (CPH * CPH);
    const int cd = idx % (CPH * CPH);
    float s = 0.f;
    for (int ck = 0; ck < 32; ck++)
        s += g_gram_part[((size_t)bh * 32 + ck) * (CPH * CPH) + cd];
    g_gram[idx] = s;
}

// ---------------- softmax ----------------
__global__ void k_softmax(const float* __restrict__ temperature)
{
    const int bh = blockIdx.x;
    const int b  = bh >> 2;
    const int h  = bh & 3;
    const int c  = threadIdx.x;
    if (c >= CPH) return;

    const float tv = temperature[h];
    const float nq = fmaxf(sqrtf(g_sumsq[0][b * C + h * CPH + c]), 1e-12f);

    float vals[CPH];
    float mx = -1e30f;
    #pragma unroll 4
    for (int d = 0; d < CPH; d++) {
        float nk = fmaxf(sqrtf(g_sumsq[1][b * C + h * CPH + d]), 1e-12f);
        float v  = g_gram[bh * (CPH * CPH) + c * CPH + d] / (nq * nk) * tv;
        vals[d] = v;
        mx = fmaxf(mx, v);
    }
    float sum = 0.f;
    #pragma unroll 4
    for (int d = 0; d < CPH; d++) {
        vals[d] = expf(vals[d] - mx);
        sum += vals[d];
    }
    const float inv = 1.f / sum;
    #pragma unroll 4
    for (int d = 0; d < CPH; d++)
        g_attn[bh * (CPH * CPH) + c * CPH + d] = vals[d] * inv;
}

// ---------------- M = proj @ blockdiag(attn) ----------------
__global__ void k_mixW(const float* __restrict__ proj_w)
{
    const int o  = blockIdx.x;
    const int b  = blockIdx.y;
    const int dg = threadIdx.x;
    const int h  = dg / CPH;
    const int d  = dg % CPH;
    float s = 0.f;
    #pragma unroll 8
    for (int cl = 0; cl < CPH; cl++)
        s += proj_w[o * C + h * CPH + cl] *
             g_attn[((size_t)(b * NH + h)) * (CPH * CPH) + cl * CPH + d];
    g_M[((size_t)b * C + o) * C + dg] = s;
}

// ---------------- launch ----------------
extern "C" void kernel_launch(void* const* d_in, const int* in_sizes, int n_in,
                              void* d_out, int out_size)
{
    const float* x      = (const float*)d_in[0];
    const float* qkv_w  = (const float*)d_in[1];
    const float* dw_w   = (const float*)d_in[2];
    const float* proj_w = (const float*)d_in[3];
    const float* temp   = (const float*)d_in[4];
    float* out = (float*)d_out;

    float *p_qkv, *p_M;
    __nv_bfloat16 *p_wh, *p_wl, *p_dh, *p_dl, *p_Mh, *p_Ml;
    cudaGetSymbolAddress((void**)&p_qkv, g_qkv);
    cudaGetSymbolAddress((void**)&p_M,   g_M);
    cudaGetSymbolAddress((void**)&p_wh,  g_w_hi);
    cudaGetSymbolAddress((void**)&p_wl,  g_w_lo);
    cudaGetSymbolAddress((void**)&p_dh,  g_dw_hi);
    cudaGetSymbolAddress((void**)&p_dl,  g_dw_lo);
    cudaGetSymbolAddress((void**)&p_Mh,  g_M_hi);
    cudaGetSymbolAddress((void**)&p_Ml,  g_M_lo);

    cudaFuncSetAttribute(gemm1_fused,    cudaFuncAttributeMaxDynamicSharedMemorySize, G1_SMEM);
    cudaFuncSetAttribute(gemm_bf16_pipe, cudaFuncAttributeMaxDynamicSharedMemorySize, GSMEM_BYTES);

    // 0) split weights to bf16 hi/lo (tiny)
    {
        int w4 = C3 * C / 4;
        k_cvt<<<(w4 + 255) / 256, 256>>>(qkv_w, p_wh, p_wl, w4);
    }

    // 1) qkv = W @ x (x converted in-kernel)
    gemm1_fused<<<dim3(HW / GBN, C3 / GBM, B), 256, G1_SMEM>>>(p_wh, p_wl, x, p_qkv);

    // 2) depthwise conv + sumsq
    k_dwconv<<<dim3(IMG / DW_ROWS, C3, B), 256>>>(dw_w);
    k_ssq_reduce<<<(B * 2 * C + 255) / 256, 256>>>();

    // 3) Gram (HMMA) + reduce
    k_gram_mma<<<dim3(32, NH, B), 128>>>();
    k_gram_reduce<<<(B * NH * CPH * CPH + 255) / 256, 256>>>();

    // 4) softmax, fold proj, split M
    k_softmax<<<B * NH, 64>>>(temp);
    k_mixW<<<dim3(C, B), C>>>(proj_w);
    {
        int m4 = B * C * C / 4;
        k_cvt<<<(m4 + 255) / 256, 256>>>(p_M, p_Mh, p_Ml, m4);
    }

    // 5) out = M @ v
    gemm_bf16_pipe<<<dim3(HW / GBN, C / GBM, B), 256, GSMEM_BYTES>>>(
        p_Mh, p_Ml, (size_t)C * C,
        p_dh + (size_t)2 * C * HW, p_dl + (size_t)2 * C * HW, (size_t)C3 * HW,
        out, (size_t)C * HW);
}